// round 1
// baseline (speedup 1.0000x reference)
#include <cuda_runtime.h>
#include <math.h>

// NestedAttention baseline: fp32 register-tiled SGEMM pipeline.
// GEMM1 (masked-A) -> per-token head-attention -> GEMM2 (+bias, masked-C).

#define DIMF     768
#define NH       12
#define HD       64
#define M_TOK    16384
#define N1       2304
#define N2       768
#define KDIM     768
#define ATT_SCALE 0.125f  // 64^-0.5

#define BM 128
#define BN 128
#define BK 16
#define TM 8
#define TN 8

// Scratch (static device globals; no allocation at runtime)
__device__ float g_qkv [(size_t)M_TOK * N1];   // 144 MB
__device__ float g_attn[(size_t)M_TOK * N2];   // 48 MB

// MODE 0: C = maskA(A) * B^T            (A = input tokens, C = g_qkv)
// MODE 1: C = A * B^T + bias, mask cols (A = g_attn,       C = output)
template<int MODE>
__global__ void __launch_bounds__(256)
gemm_kernel(const float* __restrict__ A,
            const float* __restrict__ B,
            float* __restrict__ C,
            int N,
            const int* __restrict__ expert_mask,
            const float* __restrict__ bias)
{
    __shared__ float As[BK][BM];
    __shared__ float Bs[BK][BN];
    __shared__ int   sDe[BM];

    const int m0  = blockIdx.y * BM;
    const int n0  = blockIdx.x * BN;
    const int tid = threadIdx.x;
    const int tx  = tid & 15;   // 0..15
    const int ty  = tid >> 4;   // 0..15

    if (tid < BM) {
        int e = expert_mask[m0 + tid];
        sDe[tid] = DIMF >> (3 - e);   // 96/192/384/768
    }
    __syncthreads();

    float acc[TM][TN];
    #pragma unroll
    for (int i = 0; i < TM; i++)
        #pragma unroll
        for (int j = 0; j < TN; j++) acc[i][j] = 0.f;

    for (int k0 = 0; k0 < KDIM; k0 += BK) {
        // ---- load A tile (128 rows x 16 k) as float4, store transposed ----
        #pragma unroll
        for (int it = 0; it < 2; it++) {
            int idx = tid + it * 256;       // 0..511
            int row = idx >> 2;             // 0..127
            int k4  = idx & 3;              // 0..3
            float4 av = *reinterpret_cast<const float4*>(
                &A[(size_t)(m0 + row) * KDIM + k0 + k4 * 4]);
            float v0 = av.x, v1 = av.y, v2 = av.z, v3 = av.w;
            if (MODE == 0) {
                int de = sDe[row];
                int kb = k0 + k4 * 4;
                if (kb + 0 >= de) v0 = 0.f;
                if (kb + 1 >= de) v1 = 0.f;
                if (kb + 2 >= de) v2 = 0.f;
                if (kb + 3 >= de) v3 = 0.f;
            }
            As[k4 * 4 + 0][row] = v0;
            As[k4 * 4 + 1][row] = v1;
            As[k4 * 4 + 2][row] = v2;
            As[k4 * 4 + 3][row] = v3;
        }
        // ---- load B tile (128 n-rows x 16 k) ----
        #pragma unroll
        for (int it = 0; it < 2; it++) {
            int idx = tid + it * 256;
            int row = idx >> 2;
            int k4  = idx & 3;
            float4 bv = *reinterpret_cast<const float4*>(
                &B[(size_t)(n0 + row) * KDIM + k0 + k4 * 4]);
            Bs[k4 * 4 + 0][row] = bv.x;
            Bs[k4 * 4 + 1][row] = bv.y;
            Bs[k4 * 4 + 2][row] = bv.z;
            Bs[k4 * 4 + 3][row] = bv.w;
        }
        __syncthreads();

        #pragma unroll
        for (int kk = 0; kk < BK; kk++) {
            float ar[TM], br[TN];
            #pragma unroll
            for (int i = 0; i < TM; i++) ar[i] = As[kk][ty * TM + i];
            #pragma unroll
            for (int j = 0; j < TN; j++) br[j] = Bs[kk][tx * TN + j];
            #pragma unroll
            for (int i = 0; i < TM; i++)
                #pragma unroll
                for (int j = 0; j < TN; j++)
                    acc[i][j] += ar[i] * br[j];
        }
        __syncthreads();
    }

    // ---- epilogue + store ----
    #pragma unroll
    for (int i = 0; i < TM; i++) {
        int m  = m0 + ty * TM + i;
        int de = sDe[ty * TM + i];
        #pragma unroll
        for (int j = 0; j < TN; j += 4) {
            int n = n0 + tx * TN + j;
            float4 o;
            o.x = acc[i][j + 0];
            o.y = acc[i][j + 1];
            o.z = acc[i][j + 2];
            o.w = acc[i][j + 3];
            if (MODE == 1) {
                o.x += bias[n + 0];
                o.y += bias[n + 1];
                o.z += bias[n + 2];
                o.w += bias[n + 3];
                if (n + 0 >= de) o.x = 0.f;
                if (n + 1 >= de) o.y = 0.f;
                if (n + 2 >= de) o.z = 0.f;
                if (n + 3 >= de) o.w = 0.f;
            }
            *reinterpret_cast<float4*>(&C[(size_t)m * N + n]) = o;
        }
    }
}

// Per-token attention over the heads axis: scores[12,12], softmax, AV.
__global__ void __launch_bounds__(256)
attn_kernel()
{
    __shared__ float s[N1];          // q|k|v for this token (2304 floats)
    __shared__ float s_sc[NH * NH];  // 144 scores -> attn weights

    const int tok = blockIdx.x;
    const int tid = threadIdx.x;

    const float* qkv = &g_qkv[(size_t)tok * N1];
    for (int i = tid; i < N1; i += 256) s[i] = qkv[i];
    __syncthreads();

    if (tid < NH * NH) {
        int l = tid / NH, sr = tid % NH;
        const float* q = &s[l * HD];
        const float* k = &s[DIMF + sr * HD];
        float d = 0.f;
        #pragma unroll
        for (int e = 0; e < HD; e++) d += q[e] * k[e];
        s_sc[tid] = d * ATT_SCALE;
    }
    __syncthreads();

    if (tid < NH) {
        float mx = -1e30f;
        #pragma unroll
        for (int s2 = 0; s2 < NH; s2++) mx = fmaxf(mx, s_sc[tid * NH + s2]);
        float ex[NH];
        float sum = 0.f;
        #pragma unroll
        for (int s2 = 0; s2 < NH; s2++) {
            ex[s2] = expf(s_sc[tid * NH + s2] - mx);
            sum += ex[s2];
        }
        float inv = 1.f / sum;
        #pragma unroll
        for (int s2 = 0; s2 < NH; s2++) s_sc[tid * NH + s2] = ex[s2] * inv;
    }
    __syncthreads();

    float* outp = &g_attn[(size_t)tok * DIMF];
    for (int o = tid; o < DIMF; o += 256) {
        int l = o / HD, e = o % HD;
        float a = 0.f;
        #pragma unroll
        for (int sr = 0; sr < NH; sr++)
            a += s_sc[l * NH + sr] * s[2 * DIMF + sr * HD + e];
        outp[o] = a;
    }
}

extern "C" void kernel_launch(void* const* d_in, const int* in_sizes, int n_in,
                              void* d_out, int out_size)
{
    const float* x      = (const float*)d_in[0];   // [16,1024,768]
    const int*   em     = (const int*)  d_in[1];   // [16,1024]
    const float* qkv_w  = (const float*)d_in[2];   // [2304,768]
    const float* proj_w = (const float*)d_in[3];   // [768,768]
    const float* proj_b = (const float*)d_in[4];   // [768]
    float*       out    = (float*)d_out;           // [16,1024,768]

    static float* qkv_ptr  = nullptr;
    static float* attn_ptr = nullptr;
    if (!qkv_ptr) {
        cudaGetSymbolAddress((void**)&qkv_ptr,  g_qkv);
        cudaGetSymbolAddress((void**)&attn_ptr, g_attn);
    }

    dim3 blk(256);
    dim3 grid1(N1 / BN, M_TOK / BM);   // 18 x 128
    dim3 grid2(N2 / BN, M_TOK / BM);   // 6 x 128

    gemm_kernel<0><<<grid1, blk>>>(x, qkv_w, qkv_ptr, N1, em, nullptr);
    attn_kernel<<<M_TOK, blk>>>();
    gemm_kernel<1><<<grid2, blk>>>(attn_ptr, proj_w, out, N2, em, proj_b);
}

// round 2
// speedup vs baseline: 1.6926x; 1.6926x over previous
#include <cuda_runtime.h>
#include <math.h>

// NestedAttention R1: expert-bucketed token sort + fp32 SGEMM with float4
// shared-memory fragment loads.
// sort -> GEMM1 (gathered A, K-loop bounded by tile max d_e) -> attention
// -> zero-fill out -> GEMM2 (column-blocks skipped beyond tile max d_e,
// scattered store + bias + column mask).

#define DIMF     768
#define NH       12
#define HD       64
#define M_TOK    16384
#define N1       2304
#define N2       768
#define KDIM     768
#define ATT_SCALE 0.125f

#define BM 128
#define BN 128
#define BK 16
#define TM 8
#define TN 8

// Scratch (static device globals)
__device__ float g_qkv [(size_t)M_TOK * N1];   // sorted order
__device__ float g_attn[(size_t)M_TOK * N2];   // sorted order
__device__ int   g_perm[M_TOK];                // sorted pos -> token id
__device__ int   g_de  [M_TOK];                // d_e per sorted pos
__device__ int   g_cnt[4];
__device__ int   g_off[4];
__device__ int   g_cursor[4];

// ---------------- sort pipeline ----------------
__global__ void sort_zero_kernel() {
    int t = threadIdx.x;
    if (t < 4) { g_cnt[t] = 0; g_cursor[t] = 0; }
}

__global__ void sort_hist_kernel(const int* __restrict__ em) {
    int i = blockIdx.x * blockDim.x + threadIdx.x;
    if (i < M_TOK) atomicAdd(&g_cnt[em[i]], 1);
}

__global__ void sort_scan_kernel() {
    if (threadIdx.x == 0) {
        int acc = 0;
        for (int e = 0; e < 4; e++) { g_off[e] = acc; acc += g_cnt[e]; }
    }
}

__global__ void sort_scatter_kernel(const int* __restrict__ em) {
    int i = blockIdx.x * blockDim.x + threadIdx.x;
    if (i < M_TOK) {
        int e = em[i];
        int pos = g_off[e] + atomicAdd(&g_cursor[e], 1);
        g_perm[pos] = i;
        g_de[pos]   = DIMF >> (3 - e);   // 96/192/384/768
    }
}

// ---------------- zero-fill output ----------------
__global__ void zero_out_kernel(float4* __restrict__ out, int n4) {
    int i = blockIdx.x * blockDim.x + threadIdx.x;
    float4 z = make_float4(0.f, 0.f, 0.f, 0.f);
    if (i < n4) out[i] = z;
}

// ---------------- GEMM ----------------
// MODE 0: C[sorted] = maskK(A_gathered) * B^T        (A = input x, C = g_qkv)
// MODE 1: C_scattered = A[sorted] * B^T + bias, col-masked (A = g_attn, C = out)
template<int MODE>
__global__ void __launch_bounds__(256)
gemm_kernel(const float* __restrict__ A,
            const float* __restrict__ B,
            float* __restrict__ C,
            int N,
            const float* __restrict__ bias)
{
    __shared__ float As[BK][BM];
    __shared__ float Bs[BK][BN];
    __shared__ int   sDe[BM];
    __shared__ int   sPerm[BM];
    __shared__ int   sKmax;

    const int m0  = blockIdx.y * BM;
    const int n0  = blockIdx.x * BN;
    const int tid = threadIdx.x;
    const int tx  = tid & 15;
    const int ty  = tid >> 4;

    if (tid < BM) {
        sDe[tid]   = g_de[m0 + tid];
        sPerm[tid] = g_perm[m0 + tid];
    }
    __syncthreads();
    if (tid == 0) {
        int mx = 0;
        #pragma unroll 8
        for (int r = 0; r < BM; r++) mx = max(mx, sDe[r]);
        sKmax = mx;
    }
    __syncthreads();
    const int kmax = sKmax;

    if (MODE == 1 && n0 >= kmax) return;   // whole column-block masked -> zeros already

    const int kend = (MODE == 0) ? kmax : KDIM;

    float acc[TM][TN];
    #pragma unroll
    for (int i = 0; i < TM; i++)
        #pragma unroll
        for (int j = 0; j < TN; j++) acc[i][j] = 0.f;

    for (int k0 = 0; k0 < kend; k0 += BK) {
        #pragma unroll
        for (int it = 0; it < 2; it++) {
            int idx = tid + it * 256;
            int row = idx >> 2;
            int k4  = idx & 3;
            size_t arow = (MODE == 0) ? (size_t)sPerm[row] : (size_t)(m0 + row);
            float4 av = *reinterpret_cast<const float4*>(
                &A[arow * KDIM + k0 + k4 * 4]);
            float v0 = av.x, v1 = av.y, v2 = av.z, v3 = av.w;
            if (MODE == 0) {
                int de = sDe[row];
                int kb = k0 + k4 * 4;
                if (kb + 0 >= de) v0 = 0.f;
                if (kb + 1 >= de) v1 = 0.f;
                if (kb + 2 >= de) v2 = 0.f;
                if (kb + 3 >= de) v3 = 0.f;
            }
            As[k4 * 4 + 0][row] = v0;
            As[k4 * 4 + 1][row] = v1;
            As[k4 * 4 + 2][row] = v2;
            As[k4 * 4 + 3][row] = v3;
        }
        #pragma unroll
        for (int it = 0; it < 2; it++) {
            int idx = tid + it * 256;
            int row = idx >> 2;
            int k4  = idx & 3;
            float4 bv = *reinterpret_cast<const float4*>(
                &B[(size_t)(n0 + row) * KDIM + k0 + k4 * 4]);
            Bs[k4 * 4 + 0][row] = bv.x;
            Bs[k4 * 4 + 1][row] = bv.y;
            Bs[k4 * 4 + 2][row] = bv.z;
            Bs[k4 * 4 + 3][row] = bv.w;
        }
        __syncthreads();

        #pragma unroll
        for (int kk = 0; kk < BK; kk++) {
            float4 a0 = *reinterpret_cast<const float4*>(&As[kk][ty * TM]);
            float4 a1 = *reinterpret_cast<const float4*>(&As[kk][ty * TM + 4]);
            float4 b0 = *reinterpret_cast<const float4*>(&Bs[kk][tx * TN]);
            float4 b1 = *reinterpret_cast<const float4*>(&Bs[kk][tx * TN + 4]);
            float ar[TM] = {a0.x, a0.y, a0.z, a0.w, a1.x, a1.y, a1.z, a1.w};
            float br[TN] = {b0.x, b0.y, b0.z, b0.w, b1.x, b1.y, b1.z, b1.w};
            #pragma unroll
            for (int i = 0; i < TM; i++)
                #pragma unroll
                for (int j = 0; j < TN; j++)
                    acc[i][j] += ar[i] * br[j];
        }
        __syncthreads();
    }

    #pragma unroll
    for (int i = 0; i < TM; i++) {
        int r  = ty * TM + i;
        int de = sDe[r];
        size_t crow = (MODE == 0) ? (size_t)(m0 + r) : (size_t)sPerm[r];
        #pragma unroll
        for (int j = 0; j < TN; j += 4) {
            int n = n0 + tx * TN + j;
            float4 o;
            o.x = acc[i][j + 0];
            o.y = acc[i][j + 1];
            o.z = acc[i][j + 2];
            o.w = acc[i][j + 3];
            if (MODE == 1) {
                o.x += bias[n + 0];
                o.y += bias[n + 1];
                o.z += bias[n + 2];
                o.w += bias[n + 3];
                if (n + 0 >= de) o.x = 0.f;
                if (n + 1 >= de) o.y = 0.f;
                if (n + 2 >= de) o.z = 0.f;
                if (n + 3 >= de) o.w = 0.f;
            }
            *reinterpret_cast<float4*>(&C[crow * N + n]) = o;
        }
    }
}

// ---------------- attention (per sorted token) ----------------
__global__ void __launch_bounds__(256)
attn_kernel()
{
    __shared__ float s[N1];
    __shared__ float s_sc[NH * NH];

    const int tok = blockIdx.x;
    const int tid = threadIdx.x;

    const float* qkv = &g_qkv[(size_t)tok * N1];
    for (int i = tid; i < N1; i += 256) s[i] = qkv[i];
    __syncthreads();

    if (tid < NH * NH) {
        int l = tid / NH, sr = tid % NH;
        const float* q = &s[l * HD];
        const float* k = &s[DIMF + sr * HD];
        float d = 0.f;
        #pragma unroll
        for (int e = 0; e < HD; e++) d += q[e] * k[e];
        s_sc[tid] = d * ATT_SCALE;
    }
    __syncthreads();

    if (tid < NH) {
        float mx = -1e30f;
        #pragma unroll
        for (int s2 = 0; s2 < NH; s2++) mx = fmaxf(mx, s_sc[tid * NH + s2]);
        float ex[NH];
        float sum = 0.f;
        #pragma unroll
        for (int s2 = 0; s2 < NH; s2++) {
            ex[s2] = expf(s_sc[tid * NH + s2] - mx);
            sum += ex[s2];
        }
        float inv = 1.f / sum;
        #pragma unroll
        for (int s2 = 0; s2 < NH; s2++) s_sc[tid * NH + s2] = ex[s2] * inv;
    }
    __syncthreads();

    float* outp = &g_attn[(size_t)tok * DIMF];
    for (int o = tid; o < DIMF; o += 256) {
        int l = o / HD, e = o % HD;
        float a = 0.f;
        #pragma unroll
        for (int sr = 0; sr < NH; sr++)
            a += s_sc[l * NH + sr] * s[2 * DIMF + sr * HD + e];
        outp[o] = a;
    }
}

extern "C" void kernel_launch(void* const* d_in, const int* in_sizes, int n_in,
                              void* d_out, int out_size)
{
    const float* x      = (const float*)d_in[0];
    const int*   em     = (const int*)  d_in[1];
    const float* qkv_w  = (const float*)d_in[2];
    const float* proj_w = (const float*)d_in[3];
    const float* proj_b = (const float*)d_in[4];
    float*       out    = (float*)d_out;

    static float* qkv_ptr  = nullptr;
    static float* attn_ptr = nullptr;
    if (!qkv_ptr) {
        cudaGetSymbolAddress((void**)&qkv_ptr,  g_qkv);
        cudaGetSymbolAddress((void**)&attn_ptr, g_attn);
    }

    dim3 blk(256);

    sort_zero_kernel<<<1, 32>>>();
    sort_hist_kernel<<<(M_TOK + 255) / 256, blk>>>(em);
    sort_scan_kernel<<<1, 32>>>();
    sort_scatter_kernel<<<(M_TOK + 255) / 256, blk>>>(em);

    dim3 grid1(N1 / BN, M_TOK / BM);
    gemm_kernel<0><<<grid1, blk>>>(x, qkv_w, qkv_ptr, N1, nullptr);

    attn_kernel<<<M_TOK, blk>>>();

    int n4 = M_TOK * N2 / 4;
    zero_out_kernel<<<(n4 + 255) / 256, blk>>>((float4*)out, n4);

    dim3 grid2(N2 / BN, M_TOK / BM);
    gemm_kernel<1><<<grid2, blk>>>(attn_ptr, proj_w, out, N2, proj_b);
}

// round 4
// speedup vs baseline: 3.1810x; 1.8793x over previous
#include <cuda_runtime.h>
#include <cuda_bf16.h>
#include <math.h>
#include <stdint.h>

// NestedAttention R3: expert-bucketed sort + bf16 3-term-split GEMMs on
// mma.sync.m16n8k16 tensor cores (compute_100-safe; tcgen05 PTX is rejected
// by this toolchain).  Pipeline:
//   sort -> masked/sorted bf16 hi/lo conversion -> GEMM1 (K bounded by tile
//   kmax) -> attention (emits hi/lo) -> zero-fill -> GEMM2 (col blocks
//   skipped beyond kmax, bias + col mask + row scatter).

#define DIMF 768
#define NH 12
#define HD 64
#define M_TOK 16384
#define N1 2304
#define N2 768
#define KDIM 768
#define ATT_SCALE 0.125f

#define BM 128
#define BN 128
#define BK 32
#define SKB 80                    // smem row stride bytes (32 bf16 + 16B pad)
#define TILE_B (128 * SKB)        // 10240 B
#define STAGE_B (4 * TILE_B)      // Ah, Al, Bh, Bl
#define SMEM_DYN (2 * STAGE_B)    // 81920 B

// ---------------- scratch ----------------
__device__ float         g_qkv[(size_t)M_TOK * N1];
__device__ __nv_bfloat16 g_xhi[(size_t)M_TOK * KDIM];
__device__ __nv_bfloat16 g_xlo[(size_t)M_TOK * KDIM];
__device__ __nv_bfloat16 g_ahi[(size_t)M_TOK * KDIM];
__device__ __nv_bfloat16 g_alo[(size_t)M_TOK * KDIM];
__device__ __nv_bfloat16 g_wqh[(size_t)N1 * KDIM];
__device__ __nv_bfloat16 g_wql[(size_t)N1 * KDIM];
__device__ __nv_bfloat16 g_wph[(size_t)N2 * KDIM];
__device__ __nv_bfloat16 g_wpl[(size_t)N2 * KDIM];
__device__ int g_perm[M_TOK];
__device__ int g_de[M_TOK];
__device__ int g_cnt[4], g_off[4], g_cursor[4];

// ---------------- helpers ----------------
__device__ __forceinline__ uint32_t smem_u32(const void* p) {
    uint32_t a;
    asm("{ .reg .u64 t; cvta.to.shared.u64 t, %1; cvt.u32.u64 %0, t; }" : "=r"(a) : "l"(p));
    return a;
}
__device__ __forceinline__ void cp16(uint32_t dst, const void* src) {
    asm volatile("cp.async.cg.shared.global [%0], [%1], 16;" :: "r"(dst), "l"(src));
}
__device__ __forceinline__ void cp_commit() {
    asm volatile("cp.async.commit_group;");
}
template<int N> __device__ __forceinline__ void cp_wait() {
    asm volatile("cp.async.wait_group %0;" :: "n"(N));
}
__device__ __forceinline__ void ldm_x4(uint32_t* r, uint32_t addr) {
    asm volatile("ldmatrix.sync.aligned.m8n8.x4.shared.b16 {%0,%1,%2,%3}, [%4];"
                 : "=r"(r[0]), "=r"(r[1]), "=r"(r[2]), "=r"(r[3]) : "r"(addr));
}
__device__ __forceinline__ void mma_bf16(float* c, const uint32_t* a, const uint32_t* b) {
    asm volatile(
        "mma.sync.aligned.m16n8k16.row.col.f32.bf16.bf16.f32 "
        "{%0,%1,%2,%3}, {%4,%5,%6,%7}, {%8,%9}, {%0,%1,%2,%3};"
        : "+f"(c[0]), "+f"(c[1]), "+f"(c[2]), "+f"(c[3])
        : "r"(a[0]), "r"(a[1]), "r"(a[2]), "r"(a[3]), "r"(b[0]), "r"(b[1]));
}
__device__ __forceinline__ uint32_t pk2(float a, float b) {
    __nv_bfloat162 t = __floats2bfloat162_rn(a, b);
    return *reinterpret_cast<uint32_t*>(&t);
}

// ---------------- sort pipeline ----------------
__global__ void sort_zero_kernel() {
    int t = threadIdx.x;
    if (t < 4) { g_cnt[t] = 0; g_cursor[t] = 0; }
}
__global__ void sort_hist_kernel(const int* __restrict__ em) {
    int i = blockIdx.x * blockDim.x + threadIdx.x;
    if (i < M_TOK) atomicAdd(&g_cnt[em[i]], 1);
}
__global__ void sort_scan_kernel() {
    if (threadIdx.x == 0) {
        int acc = 0;
        for (int e = 0; e < 4; e++) { g_off[e] = acc; acc += g_cnt[e]; }
    }
}
__global__ void sort_scatter_kernel(const int* __restrict__ em) {
    int i = blockIdx.x * blockDim.x + threadIdx.x;
    if (i < M_TOK) {
        int e = em[i];
        int pos = g_off[e] + atomicAdd(&g_cursor[e], 1);
        g_perm[pos] = i;
        g_de[pos]   = DIMF >> (3 - e);
    }
}

// ---------------- conversions ----------------
__global__ void __launch_bounds__(256)
convert_x_kernel(const float* __restrict__ x) {
    int i = blockIdx.x * 256 + threadIdx.x;
    if (i >= M_TOK * (KDIM / 4)) return;
    int p  = i / (KDIM / 4);
    int c4 = i % (KDIM / 4);
    int t  = g_perm[p];
    int de = g_de[p];
    float4 v = reinterpret_cast<const float4*>(x + (size_t)t * KDIM)[c4];
    int d0 = c4 * 4;
    if (d0 + 0 >= de) v.x = 0.f;
    if (d0 + 1 >= de) v.y = 0.f;
    if (d0 + 2 >= de) v.z = 0.f;
    if (d0 + 3 >= de) v.w = 0.f;
    float hx = __bfloat162float(__float2bfloat16_rn(v.x));
    float hy = __bfloat162float(__float2bfloat16_rn(v.y));
    float hz = __bfloat162float(__float2bfloat16_rn(v.z));
    float hw = __bfloat162float(__float2bfloat16_rn(v.w));
    uint2 H = make_uint2(pk2(v.x, v.y), pk2(v.z, v.w));
    uint2 L = make_uint2(pk2(v.x - hx, v.y - hy), pk2(v.z - hz, v.w - hw));
    size_t o = (size_t)p * KDIM + d0;
    *reinterpret_cast<uint2*>(&g_xhi[o]) = H;
    *reinterpret_cast<uint2*>(&g_xlo[o]) = L;
}

__global__ void __launch_bounds__(256)
convert_w_kernel(const float* __restrict__ w, __nv_bfloat16* __restrict__ hi,
                 __nv_bfloat16* __restrict__ lo, int n4) {
    int i = blockIdx.x * 256 + threadIdx.x;
    if (i >= n4) return;
    float4 v = reinterpret_cast<const float4*>(w)[i];
    float hx = __bfloat162float(__float2bfloat16_rn(v.x));
    float hy = __bfloat162float(__float2bfloat16_rn(v.y));
    float hz = __bfloat162float(__float2bfloat16_rn(v.z));
    float hw = __bfloat162float(__float2bfloat16_rn(v.w));
    uint2 H = make_uint2(pk2(v.x, v.y), pk2(v.z, v.w));
    uint2 L = make_uint2(pk2(v.x - hx, v.y - hy), pk2(v.z - hz, v.w - hw));
    *reinterpret_cast<uint2*>(&hi[(size_t)i * 4]) = H;
    *reinterpret_cast<uint2*>(&lo[(size_t)i * 4]) = L;
}

// ---------------- zero-fill ----------------
__global__ void zero_out_kernel(float4* __restrict__ out, int n4) {
    int i = blockIdx.x * blockDim.x + threadIdx.x;
    if (i < n4) out[i] = make_float4(0.f, 0.f, 0.f, 0.f);
}

// ---------------- tensor-core GEMM (mma.sync bf16, 3-term split) ----------------
// MODE 0: C[sorted] = Ahi/lo (sorted,masked) x W^T -> g_qkv; K bounded by kmax.
// MODE 1: C scattered to out; bias + column mask; n-blocks >= kmax skipped.
template<int MODE>
__global__ void __launch_bounds__(256)
gemm_mma(const __nv_bfloat16* __restrict__ Ahi, const __nv_bfloat16* __restrict__ Alo,
         const __nv_bfloat16* __restrict__ Bhi, const __nv_bfloat16* __restrict__ Blo,
         float* __restrict__ C, int N, const float* __restrict__ bias)
{
    __shared__ int sDe[BM];
    __shared__ int sPerm[BM];
    extern __shared__ char dsm[];

    const int tid  = threadIdx.x;
    const int wid  = tid >> 5;
    const int lid  = tid & 31;
    const int wrow = wid >> 1;          // 0..3 -> 32-row slice
    const int wcol = wid & 1;           // 0..1 -> 64-col slice
    const int m0   = blockIdx.y * BM;
    const int n0   = blockIdx.x * BN;

    if (tid < BM) {
        sDe[tid] = g_de[m0 + tid];
        if (MODE == 1) sPerm[tid] = g_perm[m0 + tid];
    }
    __syncthreads();
    const int kmax = sDe[BM - 1];                 // sorted ascending
    if (MODE == 1 && n0 >= kmax) return;
    const int nch = (MODE == 0) ? (kmax / BK) : (KDIM / BK);

    const uint32_t sb = smem_u32(dsm);

    // ldmatrix offsets (within a tile)
    // A (16x16 per (mt,ks)): row = wrow*32 + mt*16 + lid%16 ; byte = row*SKB + ks*32 + (lid/16)*16
    uint32_t aoff[2][2];
    #pragma unroll
    for (int mt = 0; mt < 2; mt++)
        #pragma unroll
        for (int ks = 0; ks < 2; ks++)
            aoff[mt][ks] = (uint32_t)((wrow * 32 + mt * 16 + (lid & 15)) * SKB
                                      + ks * 32 + (lid >> 4) * 16);
    // B x4 group g covers ntiles {2g, 2g+1}; matrix idx m = lid/8:
    //   n = wcol*64 + g*16 + (m>>1)*8 + lid%8 ; byte = n*SKB + ks*32 + (m&1)*16
    uint32_t boff[4][2];
    {
        int m = lid >> 3;
        #pragma unroll
        for (int g = 0; g < 4; g++)
            #pragma unroll
            for (int ks = 0; ks < 2; ks++)
                boff[g][ks] = (uint32_t)((wcol * 64 + g * 16 + (m >> 1) * 8 + (lid & 7)) * SKB
                                         + ks * 32 + (m & 1) * 16);
    }

    float c[2][8][4];
    #pragma unroll
    for (int mt = 0; mt < 2; mt++)
        #pragma unroll
        for (int nt = 0; nt < 8; nt++)
            #pragma unroll
            for (int q = 0; q < 4; q++) c[mt][nt][q] = 0.f;

    // cp.async stage fill: 512 16B segs per tile, 2 per thread per tile
    auto fill = [&](int stage, int ic) {
        const int k0 = ic * BK;
        const uint32_t st = sb + stage * STAGE_B;
        #pragma unroll
        for (int t = 0; t < 2; t++) {
            int idx = tid + t * 256;          // 0..511
            int row = idx >> 2;
            int seg = idx & 3;
            uint32_t d = st + row * SKB + seg * 16;
            const __nv_bfloat16* sa = Ahi + (size_t)(m0 + row) * KDIM + k0 + seg * 8;
            const __nv_bfloat16* sl = Alo + (size_t)(m0 + row) * KDIM + k0 + seg * 8;
            const __nv_bfloat16* sh = Bhi + (size_t)(n0 + row) * KDIM + k0 + seg * 8;
            const __nv_bfloat16* sbl= Blo + (size_t)(n0 + row) * KDIM + k0 + seg * 8;
            cp16(d + 0 * TILE_B, sa);
            cp16(d + 1 * TILE_B, sl);
            cp16(d + 2 * TILE_B, sh);
            cp16(d + 3 * TILE_B, sbl);
        }
        cp_commit();
    };

    fill(0, 0);

    for (int ic = 0; ic < nch; ic++) {
        const int b = ic & 1;
        if (ic + 1 < nch) fill(b ^ 1, ic + 1);
        if (ic + 1 < nch) cp_wait<1>(); else cp_wait<0>();
        __syncthreads();

        const uint32_t st = sb + b * STAGE_B;
        const uint32_t AH = st + 0 * TILE_B, AL = st + 1 * TILE_B;
        const uint32_t BH = st + 2 * TILE_B, BL = st + 3 * TILE_B;

        #pragma unroll
        for (int ks = 0; ks < 2; ks++) {
            uint32_t ah[2][4], al[2][4];
            #pragma unroll
            for (int mt = 0; mt < 2; mt++) {
                ldm_x4(ah[mt], AH + aoff[mt][ks]);
                ldm_x4(al[mt], AL + aoff[mt][ks]);
            }
            uint32_t bh[8][2], bl[8][2];
            #pragma unroll
            for (int g = 0; g < 4; g++) {
                uint32_t r[4];
                ldm_x4(r, BH + boff[g][ks]);
                bh[2 * g][0] = r[0]; bh[2 * g][1] = r[1];
                bh[2 * g + 1][0] = r[2]; bh[2 * g + 1][1] = r[3];
                ldm_x4(r, BL + boff[g][ks]);
                bl[2 * g][0] = r[0]; bl[2 * g][1] = r[1];
                bl[2 * g + 1][0] = r[2]; bl[2 * g + 1][1] = r[3];
            }
            #pragma unroll
            for (int mt = 0; mt < 2; mt++)
                #pragma unroll
                for (int nt = 0; nt < 8; nt++) {
                    mma_bf16(c[mt][nt], ah[mt], bh[nt]);
                    mma_bf16(c[mt][nt], ah[mt], bl[nt]);
                    mma_bf16(c[mt][nt], al[mt], bh[nt]);
                }
        }
        __syncthreads();
    }

    // epilogue: per (mt,nt): rows = wrow*32+mt*16 + lid/4 (+8); cols = wcol*64+nt*8 + (lid%4)*2
    #pragma unroll
    for (int mt = 0; mt < 2; mt++) {
        #pragma unroll
        for (int half = 0; half < 2; half++) {
            const int r    = wrow * 32 + mt * 16 + (lid >> 2) + half * 8;
            const int de   = sDe[r];
            const size_t crow = (MODE == 0) ? (size_t)(m0 + r) : (size_t)sPerm[r];
            float* dst = C + crow * (size_t)N;
            #pragma unroll
            for (int nt = 0; nt < 8; nt++) {
                const int n = n0 + wcol * 64 + nt * 8 + (lid & 3) * 2;
                float v0 = c[mt][nt][2 * half + 0];
                float v1 = c[mt][nt][2 * half + 1];
                if (MODE == 1) {
                    v0 += bias[n + 0];
                    v1 += bias[n + 1];
                    if (n + 0 >= de) v0 = 0.f;
                    if (n + 1 >= de) v1 = 0.f;
                }
                *reinterpret_cast<float2*>(dst + n) = make_float2(v0, v1);
            }
        }
    }
}

// ---------------- attention (per sorted token), emits bf16 hi/lo ----------------
__global__ void __launch_bounds__(256)
attn_kernel()
{
    __shared__ float s[N1];
    __shared__ float s_sc[NH * NH];

    const int tok = blockIdx.x;
    const int tid = threadIdx.x;

    const float4* qkv = reinterpret_cast<const float4*>(&g_qkv[(size_t)tok * N1]);
    for (int i = tid; i < N1 / 4; i += 256) reinterpret_cast<float4*>(s)[i] = qkv[i];
    __syncthreads();

    if (tid < NH * NH) {
        int l = tid / NH, sr = tid % NH;
        const float* q = &s[l * HD];
        const float* k = &s[DIMF + sr * HD];
        float d = 0.f;
        #pragma unroll
        for (int e = 0; e < HD; e++) d += q[e] * k[e];
        s_sc[tid] = d * ATT_SCALE;
    }
    __syncthreads();

    if (tid < NH) {
        float mx = -1e30f;
        #pragma unroll
        for (int s2 = 0; s2 < NH; s2++) mx = fmaxf(mx, s_sc[tid * NH + s2]);
        float ex[NH];
        float sum = 0.f;
        #pragma unroll
        for (int s2 = 0; s2 < NH; s2++) {
            ex[s2] = expf(s_sc[tid * NH + s2] - mx);
            sum += ex[s2];
        }
        float inv = 1.f / sum;
        #pragma unroll
        for (int s2 = 0; s2 < NH; s2++) s_sc[tid * NH + s2] = ex[s2] * inv;
    }
    __syncthreads();

    size_t ob = (size_t)tok * DIMF;
    for (int o = tid; o < DIMF; o += 256) {
        int l = o / HD, e = o % HD;
        float a = 0.f;
        #pragma unroll
        for (int sr = 0; sr < NH; sr++)
            a += s_sc[l * NH + sr] * s[2 * DIMF + sr * HD + e];
        __nv_bfloat16 h = __float2bfloat16_rn(a);
        g_ahi[ob + o] = h;
        g_alo[ob + o] = __float2bfloat16_rn(a - __bfloat162float(h));
    }
}

// ---------------- launch ----------------
extern "C" void kernel_launch(void* const* d_in, const int* in_sizes, int n_in,
                              void* d_out, int out_size)
{
    const float* x      = (const float*)d_in[0];
    const int*   em     = (const int*)  d_in[1];
    const float* qkv_w  = (const float*)d_in[2];
    const float* proj_w = (const float*)d_in[3];
    const float* proj_b = (const float*)d_in[4];
    float*       out    = (float*)d_out;

    static bool init_done = false;
    if (!init_done) {
        cudaFuncSetAttribute(gemm_mma<0>, cudaFuncAttributeMaxDynamicSharedMemorySize, SMEM_DYN);
        cudaFuncSetAttribute(gemm_mma<1>, cudaFuncAttributeMaxDynamicSharedMemorySize, SMEM_DYN);
        init_done = true;
    }

    static float* qkv_ptr = nullptr;
    static __nv_bfloat16 *xhi, *xlo, *ahi, *alo, *wqh, *wql, *wph, *wpl;
    if (!qkv_ptr) {
        cudaGetSymbolAddress((void**)&qkv_ptr, g_qkv);
        cudaGetSymbolAddress((void**)&xhi, g_xhi);
        cudaGetSymbolAddress((void**)&xlo, g_xlo);
        cudaGetSymbolAddress((void**)&ahi, g_ahi);
        cudaGetSymbolAddress((void**)&alo, g_alo);
        cudaGetSymbolAddress((void**)&wqh, g_wqh);
        cudaGetSymbolAddress((void**)&wql, g_wql);
        cudaGetSymbolAddress((void**)&wph, g_wph);
        cudaGetSymbolAddress((void**)&wpl, g_wpl);
    }

    dim3 blk(256);

    sort_zero_kernel<<<1, 32>>>();
    sort_hist_kernel<<<(M_TOK + 255) / 256, blk>>>(em);
    sort_scan_kernel<<<1, 32>>>();
    sort_scatter_kernel<<<(M_TOK + 255) / 256, blk>>>(em);

    convert_w_kernel<<<(N1 * KDIM / 4 + 255) / 256, blk>>>(qkv_w, wqh, wql, N1 * KDIM / 4);
    convert_w_kernel<<<(N2 * KDIM / 4 + 255) / 256, blk>>>(proj_w, wph, wpl, N2 * KDIM / 4);
    convert_x_kernel<<<(M_TOK * (KDIM / 4) + 255) / 256, blk>>>(x);

    dim3 grid1(N1 / BN, M_TOK / BM);   // 18 x 128
    gemm_mma<0><<<grid1, blk, SMEM_DYN>>>(xhi, xlo, wqh, wql, qkv_ptr, N1, nullptr);

    attn_kernel<<<M_TOK, blk>>>();

    int n4 = M_TOK * N2 / 4;
    zero_out_kernel<<<(n4 + 255) / 256, blk>>>((float4*)out, n4);

    dim3 grid2(N2 / BN, M_TOK / BM);   // 6 x 128
    gemm_mma<1><<<grid2, blk, SMEM_DYN>>>(ahi, alo, wph, wpl, out, N2, proj_b);
}

// round 6
// speedup vs baseline: 3.2081x; 1.0085x over previous
#include <cuda_runtime.h>
#include <cuda_bf16.h>
#include <math.h>
#include <stdint.h>

// NestedAttention R5 (resubmit — previous run died to container infra failure,
// kernel never executed): bucketed sort (block-range, low-contention) + bf16
// 3-term-split GEMMs on mma.sync.m16n8k16, single-sync double-buffered
// mainloop. Order: sort(3) -> convw -> convx -> GEMM1 -> attn -> zero -> GEMM2.

#define DIMF 768
#define NH 12
#define HD 64
#define M_TOK 16384
#define N1 2304
#define N2 768
#define KDIM 768
#define ATT_SCALE 0.125f

#define BM 128
#define BN 128
#define BK 32
#define SKB 80                    // smem row stride bytes (32 bf16 + 16B pad)
#define TILE_B (128 * SKB)        // 10240 B
#define STAGE_B (4 * TILE_B)      // Ah, Al, Bh, Bl
#define SMEM_DYN (2 * STAGE_B)    // 81920 B

// ---------------- scratch ----------------
__device__ float         g_qkv[(size_t)M_TOK * N1];
__device__ __nv_bfloat16 g_xhi[(size_t)M_TOK * KDIM];
__device__ __nv_bfloat16 g_xlo[(size_t)M_TOK * KDIM];
__device__ __nv_bfloat16 g_ahi[(size_t)M_TOK * KDIM];
__device__ __nv_bfloat16 g_alo[(size_t)M_TOK * KDIM];
__device__ __nv_bfloat16 g_wqh[(size_t)N1 * KDIM];
__device__ __nv_bfloat16 g_wql[(size_t)N1 * KDIM];
__device__ __nv_bfloat16 g_wph[(size_t)N2 * KDIM];
__device__ __nv_bfloat16 g_wpl[(size_t)N2 * KDIM];
__device__ int g_perm[M_TOK];
__device__ int g_de[M_TOK];
__device__ int g_bh[64 * 4];      // per-block expert histogram
__device__ int g_boff[64 * 4];    // per-(block,expert) global start

// ---------------- helpers ----------------
__device__ __forceinline__ uint32_t smem_u32(const void* p) {
    uint32_t a;
    asm("{ .reg .u64 t; cvta.to.shared.u64 t, %1; cvt.u32.u64 %0, t; }" : "=r"(a) : "l"(p));
    return a;
}
__device__ __forceinline__ void cp16(uint32_t dst, const void* src) {
    asm volatile("cp.async.cg.shared.global [%0], [%1], 16;" :: "r"(dst), "l"(src));
}
__device__ __forceinline__ void cp_commit() {
    asm volatile("cp.async.commit_group;");
}
template<int N> __device__ __forceinline__ void cp_wait() {
    asm volatile("cp.async.wait_group %0;" :: "n"(N));
}
__device__ __forceinline__ void ldm_x4(uint32_t* r, uint32_t addr) {
    asm volatile("ldmatrix.sync.aligned.m8n8.x4.shared.b16 {%0,%1,%2,%3}, [%4];"
                 : "=r"(r[0]), "=r"(r[1]), "=r"(r[2]), "=r"(r[3]) : "r"(addr));
}
__device__ __forceinline__ void mma_bf16(float* c, const uint32_t* a, const uint32_t* b) {
    asm volatile(
        "mma.sync.aligned.m16n8k16.row.col.f32.bf16.bf16.f32 "
        "{%0,%1,%2,%3}, {%4,%5,%6,%7}, {%8,%9}, {%0,%1,%2,%3};"
        : "+f"(c[0]), "+f"(c[1]), "+f"(c[2]), "+f"(c[3])
        : "r"(a[0]), "r"(a[1]), "r"(a[2]), "r"(a[3]), "r"(b[0]), "r"(b[1]));
}
__device__ __forceinline__ uint32_t pk2(float a, float b) {
    __nv_bfloat162 t = __floats2bfloat162_rn(a, b);
    return *reinterpret_cast<uint32_t*>(&t);
}

// ---------------- sort (3 kernels, no global zero / low contention) ----------------
__global__ void sort_hist_kernel(const int* __restrict__ em) {   // 64 x 256
    __shared__ int h[4];
    int tid = threadIdx.x, b = blockIdx.x;
    if (tid < 4) h[tid] = 0;
    __syncthreads();
    atomicAdd(&h[em[b * 256 + tid]], 1);
    __syncthreads();
    if (tid < 4) g_bh[b * 4 + tid] = h[tid];
}
__global__ void sort_scan_kernel() {                              // 1 x 32
    if (threadIdx.x == 0) {
        int acc = 0;
        for (int e = 0; e < 4; e++)
            for (int b = 0; b < 64; b++) { g_boff[b * 4 + e] = acc; acc += g_bh[b * 4 + e]; }
    }
}
__global__ void sort_scatter_kernel(const int* __restrict__ em) { // 64 x 256
    __shared__ int cur[4];
    int tid = threadIdx.x, b = blockIdx.x;
    if (tid < 4) cur[tid] = g_boff[b * 4 + tid];
    __syncthreads();
    int i = b * 256 + tid;
    int e = em[i];
    int pos = atomicAdd(&cur[e], 1);
    g_perm[pos] = i;
    g_de[pos]   = DIMF >> (3 - e);
}

// ---------------- conversions ----------------
// both weight matrices in one launch
__global__ void __launch_bounds__(256)
convert_w_kernel(const float* __restrict__ wq, const float* __restrict__ wp) {
    int i = blockIdx.x * 256 + threadIdx.x;             // float4 index
    const int NQ = N1 * (KDIM / 4);
    if (i >= NQ + N2 * (KDIM / 4)) return;
    const float* src;
    __nv_bfloat16 *hi, *lo;
    int j;
    if (i < NQ) { src = wq; hi = g_wqh; lo = g_wql; j = i; }
    else        { src = wp; hi = g_wph; lo = g_wpl; j = i - NQ; }
    float4 v = reinterpret_cast<const float4*>(src)[j];
    float hx = __bfloat162float(__float2bfloat16_rn(v.x));
    float hy = __bfloat162float(__float2bfloat16_rn(v.y));
    float hz = __bfloat162float(__float2bfloat16_rn(v.z));
    float hw = __bfloat162float(__float2bfloat16_rn(v.w));
    uint2 H = make_uint2(pk2(v.x, v.y), pk2(v.z, v.w));
    uint2 L = make_uint2(pk2(v.x - hx, v.y - hy), pk2(v.z - hz, v.w - hw));
    *reinterpret_cast<uint2*>(&hi[(size_t)j * 4]) = H;
    *reinterpret_cast<uint2*>(&lo[(size_t)j * 4]) = L;
}

__global__ void __launch_bounds__(256)
convert_x_kernel(const float* __restrict__ x) {
    int i = blockIdx.x * 256 + threadIdx.x;
    if (i >= M_TOK * (KDIM / 4)) return;
    int p  = i / (KDIM / 4);
    int c4 = i % (KDIM / 4);
    int t  = g_perm[p];
    int de = g_de[p];
    float4 v = reinterpret_cast<const float4*>(x + (size_t)t * KDIM)[c4];
    int d0 = c4 * 4;
    if (d0 + 0 >= de) v.x = 0.f;
    if (d0 + 1 >= de) v.y = 0.f;
    if (d0 + 2 >= de) v.z = 0.f;
    if (d0 + 3 >= de) v.w = 0.f;
    float hx = __bfloat162float(__float2bfloat16_rn(v.x));
    float hy = __bfloat162float(__float2bfloat16_rn(v.y));
    float hz = __bfloat162float(__float2bfloat16_rn(v.z));
    float hw = __bfloat162float(__float2bfloat16_rn(v.w));
    uint2 H = make_uint2(pk2(v.x, v.y), pk2(v.z, v.w));
    uint2 L = make_uint2(pk2(v.x - hx, v.y - hy), pk2(v.z - hz, v.w - hw));
    size_t o = (size_t)p * KDIM + d0;
    *reinterpret_cast<uint2*>(&g_xhi[o]) = H;
    *reinterpret_cast<uint2*>(&g_xlo[o]) = L;
}

// ---------------- zero-fill ----------------
__global__ void zero_out_kernel(float4* __restrict__ out, int n4) {
    int i = blockIdx.x * blockDim.x + threadIdx.x;
    if (i < n4) out[i] = make_float4(0.f, 0.f, 0.f, 0.f);
}

// ---------------- tensor-core GEMM (mma.sync bf16, 3-term split) ----------------
template<int MODE>
__global__ void __launch_bounds__(256)
gemm_mma(const __nv_bfloat16* __restrict__ Ahi, const __nv_bfloat16* __restrict__ Alo,
         const __nv_bfloat16* __restrict__ Bhi, const __nv_bfloat16* __restrict__ Blo,
         float* __restrict__ C, int N, const float* __restrict__ bias)
{
    __shared__ int sDe[BM];
    __shared__ int sPerm[BM];
    extern __shared__ char dsm[];

    const int tid  = threadIdx.x;
    const int wid  = tid >> 5;
    const int lid  = tid & 31;
    const int wrow = wid >> 1;
    const int wcol = wid & 1;
    const int m0   = blockIdx.y * BM;
    const int n0   = blockIdx.x * BN;

    if (tid < BM) {
        sDe[tid] = g_de[m0 + tid];
        if (MODE == 1) sPerm[tid] = g_perm[m0 + tid];
    }
    __syncthreads();
    const int kmax = sDe[BM - 1];                 // sorted ascending
    if (MODE == 1 && n0 >= kmax) return;
    const int nch = (MODE == 0) ? (kmax / BK) : (KDIM / BK);

    const uint32_t sb = smem_u32(dsm);

    uint32_t aoff[2][2];
    #pragma unroll
    for (int mt = 0; mt < 2; mt++)
        #pragma unroll
        for (int ks = 0; ks < 2; ks++)
            aoff[mt][ks] = (uint32_t)((wrow * 32 + mt * 16 + (lid & 15)) * SKB
                                      + ks * 32 + (lid >> 4) * 16);
    uint32_t boff[4][2];
    {
        int m = lid >> 3;
        #pragma unroll
        for (int g = 0; g < 4; g++)
            #pragma unroll
            for (int ks = 0; ks < 2; ks++)
                boff[g][ks] = (uint32_t)((wcol * 64 + g * 16 + (m >> 1) * 8 + (lid & 7)) * SKB
                                         + ks * 32 + (m & 1) * 16);
    }

    float c[2][8][4];
    #pragma unroll
    for (int mt = 0; mt < 2; mt++)
        #pragma unroll
        for (int nt = 0; nt < 8; nt++)
            #pragma unroll
            for (int q = 0; q < 4; q++) c[mt][nt][q] = 0.f;

    auto fill = [&](int stage, int ic) {
        const int k0 = ic * BK;
        const uint32_t st = sb + stage * STAGE_B;
        #pragma unroll
        for (int t = 0; t < 2; t++) {
            int idx = tid + t * 256;
            int row = idx >> 2;
            int seg = idx & 3;
            uint32_t d = st + row * SKB + seg * 16;
            const __nv_bfloat16* sa = Ahi + (size_t)(m0 + row) * KDIM + k0 + seg * 8;
            const __nv_bfloat16* sl = Alo + (size_t)(m0 + row) * KDIM + k0 + seg * 8;
            const __nv_bfloat16* sh = Bhi + (size_t)(n0 + row) * KDIM + k0 + seg * 8;
            const __nv_bfloat16* sbl= Blo + (size_t)(n0 + row) * KDIM + k0 + seg * 8;
            cp16(d + 0 * TILE_B, sa);
            cp16(d + 1 * TILE_B, sl);
            cp16(d + 2 * TILE_B, sh);
            cp16(d + 3 * TILE_B, sbl);
        }
        cp_commit();
    };

    fill(0, 0);

    for (int ic = 0; ic < nch; ic++) {
        const int b = ic & 1;
        cp_wait<0>();           // stage b's data landed
        __syncthreads();        // also: everyone done reading stage b^1
        if (ic + 1 < nch) fill(b ^ 1, ic + 1);

        const uint32_t st = sb + b * STAGE_B;
        const uint32_t AH = st + 0 * TILE_B, AL = st + 1 * TILE_B;
        const uint32_t BH = st + 2 * TILE_B, BL = st + 3 * TILE_B;

        #pragma unroll
        for (int ks = 0; ks < 2; ks++) {
            uint32_t ah[2][4], al[2][4];
            #pragma unroll
            for (int mt = 0; mt < 2; mt++) {
                ldm_x4(ah[mt], AH + aoff[mt][ks]);
                ldm_x4(al[mt], AL + aoff[mt][ks]);
            }
            uint32_t bh[8][2], bl[8][2];
            #pragma unroll
            for (int g = 0; g < 4; g++) {
                uint32_t r[4];
                ldm_x4(r, BH + boff[g][ks]);
                bh[2 * g][0] = r[0]; bh[2 * g][1] = r[1];
                bh[2 * g + 1][0] = r[2]; bh[2 * g + 1][1] = r[3];
                ldm_x4(r, BL + boff[g][ks]);
                bl[2 * g][0] = r[0]; bl[2 * g][1] = r[1];
                bl[2 * g + 1][0] = r[2]; bl[2 * g + 1][1] = r[3];
            }
            #pragma unroll
            for (int mt = 0; mt < 2; mt++)
                #pragma unroll
                for (int nt = 0; nt < 8; nt++) {
                    mma_bf16(c[mt][nt], ah[mt], bh[nt]);
                    mma_bf16(c[mt][nt], ah[mt], bl[nt]);
                    mma_bf16(c[mt][nt], al[mt], bh[nt]);
                }
        }
    }

    __syncthreads();

    #pragma unroll
    for (int mt = 0; mt < 2; mt++) {
        #pragma unroll
        for (int half = 0; half < 2; half++) {
            const int r    = wrow * 32 + mt * 16 + (lid >> 2) + half * 8;
            const int de   = sDe[r];
            const size_t crow = (MODE == 0) ? (size_t)(m0 + r) : (size_t)sPerm[r];
            float* dst = C + crow * (size_t)N;
            #pragma unroll
            for (int nt = 0; nt < 8; nt++) {
                const int n = n0 + wcol * 64 + nt * 8 + (lid & 3) * 2;
                float v0 = c[mt][nt][2 * half + 0];
                float v1 = c[mt][nt][2 * half + 1];
                if (MODE == 1) {
                    v0 += bias[n + 0];
                    v1 += bias[n + 1];
                    if (n + 0 >= de) v0 = 0.f;
                    if (n + 1 >= de) v1 = 0.f;
                }
                *reinterpret_cast<float2*>(dst + n) = make_float2(v0, v1);
            }
        }
    }
}

// ---------------- attention ----------------
__global__ void __launch_bounds__(256)
attn_kernel()
{
    __shared__ float s[N1];
    __shared__ float s_sc[NH * NH];

    const int tok = blockIdx.x;
    const int tid = threadIdx.x;

    const float4* qkv = reinterpret_cast<const float4*>(&g_qkv[(size_t)tok * N1]);
    for (int i = tid; i < N1 / 4; i += 256) reinterpret_cast<float4*>(s)[i] = qkv[i];
    __syncthreads();

    if (tid < NH * NH) {
        int l = tid / NH, sr = tid % NH;
        const float* q = &s[l * HD];
        const float* k = &s[DIMF + sr * HD];
        float d = 0.f;
        #pragma unroll
        for (int e = 0; e < HD; e++) d += q[e] * k[e];
        s_sc[tid] = d * ATT_SCALE;
    }
    __syncthreads();

    if (tid < NH) {
        float mx = -1e30f;
        #pragma unroll
        for (int s2 = 0; s2 < NH; s2++) mx = fmaxf(mx, s_sc[tid * NH + s2]);
        float ex[NH];
        float sum = 0.f;
        #pragma unroll
        for (int s2 = 0; s2 < NH; s2++) {
            ex[s2] = expf(s_sc[tid * NH + s2] - mx);
            sum += ex[s2];
        }
        float inv = 1.f / sum;
        #pragma unroll
        for (int s2 = 0; s2 < NH; s2++) s_sc[tid * NH + s2] = ex[s2] * inv;
    }
    __syncthreads();

    size_t ob = (size_t)tok * DIMF;
    for (int o = tid; o < DIMF; o += 256) {
        int l = o / HD, e = o % HD;
        float a = 0.f;
        #pragma unroll
        for (int sr = 0; sr < NH; sr++)
            a += s_sc[l * NH + sr] * s[2 * DIMF + sr * HD + e];
        __nv_bfloat16 h = __float2bfloat16_rn(a);
        g_ahi[ob + o] = h;
        g_alo[ob + o] = __float2bfloat16_rn(a - __bfloat162float(h));
    }
}

// ---------------- launch ----------------
extern "C" void kernel_launch(void* const* d_in, const int* in_sizes, int n_in,
                              void* d_out, int out_size)
{
    const float* x      = (const float*)d_in[0];
    const int*   em     = (const int*)  d_in[1];
    const float* qkv_w  = (const float*)d_in[2];
    const float* proj_w = (const float*)d_in[3];
    const float* proj_b = (const float*)d_in[4];
    float*       out    = (float*)d_out;

    static bool init_done = false;
    if (!init_done) {
        cudaFuncSetAttribute(gemm_mma<0>, cudaFuncAttributeMaxDynamicSharedMemorySize, SMEM_DYN);
        cudaFuncSetAttribute(gemm_mma<1>, cudaFuncAttributeMaxDynamicSharedMemorySize, SMEM_DYN);
        init_done = true;
    }

    static float* qkv_ptr = nullptr;
    static __nv_bfloat16 *xhi, *xlo, *ahi, *alo, *wqh, *wql, *wph, *wpl;
    if (!qkv_ptr) {
        cudaGetSymbolAddress((void**)&qkv_ptr, g_qkv);
        cudaGetSymbolAddress((void**)&xhi, g_xhi);
        cudaGetSymbolAddress((void**)&xlo, g_xlo);
        cudaGetSymbolAddress((void**)&ahi, g_ahi);
        cudaGetSymbolAddress((void**)&alo, g_alo);
        cudaGetSymbolAddress((void**)&wqh, g_wqh);
        cudaGetSymbolAddress((void**)&wql, g_wql);
        cudaGetSymbolAddress((void**)&wph, g_wph);
        cudaGetSymbolAddress((void**)&wpl, g_wpl);
    }

    dim3 blk(256);

    sort_hist_kernel<<<64, blk>>>(em);                                        // 1
    sort_scan_kernel<<<1, 32>>>();                                            // 2
    sort_scatter_kernel<<<64, blk>>>(em);                                     // 3
    {
        int tot = (N1 + N2) * (KDIM / 4);
        convert_w_kernel<<<(tot + 255) / 256, blk>>>(qkv_w, proj_w);          // 4
    }
    convert_x_kernel<<<(M_TOK * (KDIM / 4) + 255) / 256, blk>>>(x);           // 5

    dim3 grid1(N1 / BN, M_TOK / BM);
    gemm_mma<0><<<grid1, blk, SMEM_DYN>>>(xhi, xlo, wqh, wql, qkv_ptr, N1, nullptr); // 6

    attn_kernel<<<M_TOK, blk>>>();                                            // 7

    int n4 = M_TOK * N2 / 4;
    zero_out_kernel<<<(n4 + 255) / 256, blk>>>((float4*)out, n4);             // 8

    dim3 grid2(N2 / BN, M_TOK / BM);
    gemm_mma<1><<<grid2, blk, SMEM_DYN>>>(ahi, alo, wph, wpl, out, N2, proj_b); // 9
}

// round 8
// speedup vs baseline: 4.1656x; 1.2984x over previous
#include <cuda_runtime.h>
#include <cuda_bf16.h>
#include <math.h>
#include <stdint.h>

// NestedAttention R7 (resubmit — infra container failure, kernel never ran):
// GEMM rewarped to 4 warps x (64x64) tiles to break the smem-port /
// tensor-issue co-limit (96KB -> 64KB LDSM traffic per chunk).
// Attention v2: 2 tokens/block, vectorized conflict-aware score phase.

#define DIMF 768
#define NH 12
#define HD 64
#define M_TOK 16384
#define N1 2304
#define N2 768
#define KDIM 768
#define ATT_SCALE 0.125f

#define BM 128
#define BN 128
#define BK 32
#define SKB 80                    // smem row stride bytes (32 bf16 + 16B pad)
#define TILE_B (128 * SKB)        // 10240 B
#define STAGE_B (4 * TILE_B)      // Ah, Al, Bh, Bl
#define SMEM_DYN (2 * STAGE_B)    // 81920 B

// ---------------- scratch ----------------
__device__ float         g_qkv[(size_t)M_TOK * N1];
__device__ __nv_bfloat16 g_xhi[(size_t)M_TOK * KDIM];
__device__ __nv_bfloat16 g_xlo[(size_t)M_TOK * KDIM];
__device__ __nv_bfloat16 g_ahi[(size_t)M_TOK * KDIM];
__device__ __nv_bfloat16 g_alo[(size_t)M_TOK * KDIM];
__device__ __nv_bfloat16 g_wqh[(size_t)N1 * KDIM];
__device__ __nv_bfloat16 g_wql[(size_t)N1 * KDIM];
__device__ __nv_bfloat16 g_wph[(size_t)N2 * KDIM];
__device__ __nv_bfloat16 g_wpl[(size_t)N2 * KDIM];
__device__ int g_perm[M_TOK];
__device__ int g_de[M_TOK];
__device__ int g_bh[64 * 4];
__device__ int g_boff[64 * 4];

// ---------------- helpers ----------------
__device__ __forceinline__ uint32_t smem_u32(const void* p) {
    uint32_t a;
    asm("{ .reg .u64 t; cvta.to.shared.u64 t, %1; cvt.u32.u64 %0, t; }" : "=r"(a) : "l"(p));
    return a;
}
__device__ __forceinline__ void cp16(uint32_t dst, const void* src) {
    asm volatile("cp.async.cg.shared.global [%0], [%1], 16;" :: "r"(dst), "l"(src));
}
__device__ __forceinline__ void cp_commit() {
    asm volatile("cp.async.commit_group;");
}
template<int N> __device__ __forceinline__ void cp_wait() {
    asm volatile("cp.async.wait_group %0;" :: "n"(N));
}
__device__ __forceinline__ void ldm_x4(uint32_t* r, uint32_t addr) {
    asm volatile("ldmatrix.sync.aligned.m8n8.x4.shared.b16 {%0,%1,%2,%3}, [%4];"
                 : "=r"(r[0]), "=r"(r[1]), "=r"(r[2]), "=r"(r[3]) : "r"(addr));
}
__device__ __forceinline__ void mma_bf16(float* c, const uint32_t* a, const uint32_t* b) {
    asm volatile(
        "mma.sync.aligned.m16n8k16.row.col.f32.bf16.bf16.f32 "
        "{%0,%1,%2,%3}, {%4,%5,%6,%7}, {%8,%9}, {%0,%1,%2,%3};"
        : "+f"(c[0]), "+f"(c[1]), "+f"(c[2]), "+f"(c[3])
        : "r"(a[0]), "r"(a[1]), "r"(a[2]), "r"(a[3]), "r"(b[0]), "r"(b[1]));
}
__device__ __forceinline__ uint32_t pk2(float a, float b) {
    __nv_bfloat162 t = __floats2bfloat162_rn(a, b);
    return *reinterpret_cast<uint32_t*>(&t);
}

// ---------------- sort ----------------
__global__ void sort_hist_kernel(const int* __restrict__ em) {
    __shared__ int h[4];
    int tid = threadIdx.x, b = blockIdx.x;
    if (tid < 4) h[tid] = 0;
    __syncthreads();
    atomicAdd(&h[em[b * 256 + tid]], 1);
    __syncthreads();
    if (tid < 4) g_bh[b * 4 + tid] = h[tid];
}
__global__ void sort_scan_kernel() {
    if (threadIdx.x == 0) {
        int acc = 0;
        for (int e = 0; e < 4; e++)
            for (int b = 0; b < 64; b++) { g_boff[b * 4 + e] = acc; acc += g_bh[b * 4 + e]; }
    }
}
__global__ void sort_scatter_kernel(const int* __restrict__ em) {
    __shared__ int cur[4];
    int tid = threadIdx.x, b = blockIdx.x;
    if (tid < 4) cur[tid] = g_boff[b * 4 + tid];
    __syncthreads();
    int i = b * 256 + tid;
    int e = em[i];
    int pos = atomicAdd(&cur[e], 1);
    g_perm[pos] = i;
    g_de[pos]   = DIMF >> (3 - e);
}

// ---------------- conversions ----------------
__global__ void __launch_bounds__(256)
convert_w_kernel(const float* __restrict__ wq, const float* __restrict__ wp) {
    int i = blockIdx.x * 256 + threadIdx.x;
    const int NQ = N1 * (KDIM / 4);
    if (i >= NQ + N2 * (KDIM / 4)) return;
    const float* src;
    __nv_bfloat16 *hi, *lo;
    int j;
    if (i < NQ) { src = wq; hi = g_wqh; lo = g_wql; j = i; }
    else        { src = wp; hi = g_wph; lo = g_wpl; j = i - NQ; }
    float4 v = reinterpret_cast<const float4*>(src)[j];
    float hx = __bfloat162float(__float2bfloat16_rn(v.x));
    float hy = __bfloat162float(__float2bfloat16_rn(v.y));
    float hz = __bfloat162float(__float2bfloat16_rn(v.z));
    float hw = __bfloat162float(__float2bfloat16_rn(v.w));
    uint2 H = make_uint2(pk2(v.x, v.y), pk2(v.z, v.w));
    uint2 L = make_uint2(pk2(v.x - hx, v.y - hy), pk2(v.z - hz, v.w - hw));
    *reinterpret_cast<uint2*>(&hi[(size_t)j * 4]) = H;
    *reinterpret_cast<uint2*>(&lo[(size_t)j * 4]) = L;
}

__global__ void __launch_bounds__(256)
convert_x_kernel(const float* __restrict__ x) {
    int i = blockIdx.x * 256 + threadIdx.x;
    if (i >= M_TOK * (KDIM / 4)) return;
    int p  = i / (KDIM / 4);
    int c4 = i % (KDIM / 4);
    int t  = g_perm[p];
    int de = g_de[p];
    float4 v = reinterpret_cast<const float4*>(x + (size_t)t * KDIM)[c4];
    int d0 = c4 * 4;
    if (d0 + 0 >= de) v.x = 0.f;
    if (d0 + 1 >= de) v.y = 0.f;
    if (d0 + 2 >= de) v.z = 0.f;
    if (d0 + 3 >= de) v.w = 0.f;
    float hx = __bfloat162float(__float2bfloat16_rn(v.x));
    float hy = __bfloat162float(__float2bfloat16_rn(v.y));
    float hz = __bfloat162float(__float2bfloat16_rn(v.z));
    float hw = __bfloat162float(__float2bfloat16_rn(v.w));
    uint2 H = make_uint2(pk2(v.x, v.y), pk2(v.z, v.w));
    uint2 L = make_uint2(pk2(v.x - hx, v.y - hy), pk2(v.z - hz, v.w - hw));
    size_t o = (size_t)p * KDIM + d0;
    *reinterpret_cast<uint2*>(&g_xhi[o]) = H;
    *reinterpret_cast<uint2*>(&g_xlo[o]) = L;
}

// ---------------- zero-fill ----------------
__global__ void zero_out_kernel(float4* __restrict__ out, int n4) {
    int i = blockIdx.x * blockDim.x + threadIdx.x;
    if (i < n4) out[i] = make_float4(0.f, 0.f, 0.f, 0.f);
}

// ---------------- tensor-core GEMM: 4 warps, 64x64 warp tiles ----------------
template<int MODE>
__global__ void __launch_bounds__(128, 2)
gemm_mma(const __nv_bfloat16* __restrict__ Ahi, const __nv_bfloat16* __restrict__ Alo,
         const __nv_bfloat16* __restrict__ Bhi, const __nv_bfloat16* __restrict__ Blo,
         float* __restrict__ C, int N, const float* __restrict__ bias)
{
    __shared__ int sDe[BM];
    __shared__ int sPerm[BM];
    extern __shared__ char dsm[];

    const int tid  = threadIdx.x;
    const int wid  = tid >> 5;
    const int lid  = tid & 31;
    const int wrow = wid >> 1;          // 0..1 -> 64-row slice
    const int wcol = wid & 1;           // 0..1 -> 64-col slice
    const int m0   = blockIdx.y * BM;
    const int n0   = blockIdx.x * BN;

    sDe[tid] = g_de[m0 + tid];
    if (MODE == 1) sPerm[tid] = g_perm[m0 + tid];
    __syncthreads();
    const int kmax = sDe[BM - 1];                 // sorted ascending
    if (MODE == 1 && n0 >= kmax) return;
    const int nch = (MODE == 0) ? (kmax / BK) : (KDIM / BK);

    const uint32_t sb = smem_u32(dsm);

    // A fragment smem offsets: 4 m-tiles of 16 rows each within 64-row warp slice
    uint32_t aoff[4][2];
    #pragma unroll
    for (int mt = 0; mt < 4; mt++)
        #pragma unroll
        for (int ks = 0; ks < 2; ks++)
            aoff[mt][ks] = (uint32_t)((wrow * 64 + mt * 16 + (lid & 15)) * SKB
                                      + ks * 32 + (lid >> 4) * 16);
    // B groups: g covers nt {2g,2g+1}
    uint32_t boff[4][2];
    {
        int m = lid >> 3;
        #pragma unroll
        for (int g = 0; g < 4; g++)
            #pragma unroll
            for (int ks = 0; ks < 2; ks++)
                boff[g][ks] = (uint32_t)((wcol * 64 + g * 16 + (m >> 1) * 8 + (lid & 7)) * SKB
                                         + ks * 32 + (m & 1) * 16);
    }

    float c[4][8][4];
    #pragma unroll
    for (int mt = 0; mt < 4; mt++)
        #pragma unroll
        for (int nt = 0; nt < 8; nt++)
            #pragma unroll
            for (int q = 0; q < 4; q++) c[mt][nt][q] = 0.f;

    // fill: 512 16B segs per tile, 4 per thread per tile (128 threads)
    auto fill = [&](int stage, int ic) {
        const int k0 = ic * BK;
        const uint32_t st = sb + stage * STAGE_B;
        #pragma unroll
        for (int t = 0; t < 4; t++) {
            int idx = tid + t * 128;
            int row = idx >> 2;
            int seg = idx & 3;
            uint32_t d = st + row * SKB + seg * 16;
            const __nv_bfloat16* sa = Ahi + (size_t)(m0 + row) * KDIM + k0 + seg * 8;
            const __nv_bfloat16* sl = Alo + (size_t)(m0 + row) * KDIM + k0 + seg * 8;
            const __nv_bfloat16* sh = Bhi + (size_t)(n0 + row) * KDIM + k0 + seg * 8;
            const __nv_bfloat16* sbl= Blo + (size_t)(n0 + row) * KDIM + k0 + seg * 8;
            cp16(d + 0 * TILE_B, sa);
            cp16(d + 1 * TILE_B, sl);
            cp16(d + 2 * TILE_B, sh);
            cp16(d + 3 * TILE_B, sbl);
        }
        cp_commit();
    };

    fill(0, 0);

    for (int ic = 0; ic < nch; ic++) {
        const int b = ic & 1;
        cp_wait<0>();
        __syncthreads();
        if (ic + 1 < nch) fill(b ^ 1, ic + 1);

        const uint32_t st = sb + b * STAGE_B;
        const uint32_t AH = st + 0 * TILE_B, AL = st + 1 * TILE_B;
        const uint32_t BH = st + 2 * TILE_B, BL = st + 3 * TILE_B;

        #pragma unroll
        for (int ks = 0; ks < 2; ks++) {
            uint32_t ah[4][4], al[4][4];
            #pragma unroll
            for (int mt = 0; mt < 4; mt++) {
                ldm_x4(ah[mt], AH + aoff[mt][ks]);
                ldm_x4(al[mt], AL + aoff[mt][ks]);
            }
            #pragma unroll
            for (int g = 0; g < 4; g++) {
                uint32_t rh[4], rl[4];
                ldm_x4(rh, BH + boff[g][ks]);
                ldm_x4(rl, BL + boff[g][ks]);
                #pragma unroll
                for (int mt = 0; mt < 4; mt++) {
                    mma_bf16(c[mt][2 * g + 0], ah[mt], rh + 0);
                    mma_bf16(c[mt][2 * g + 0], ah[mt], rl + 0);
                    mma_bf16(c[mt][2 * g + 0], al[mt], rh + 0);
                    mma_bf16(c[mt][2 * g + 1], ah[mt], rh + 2);
                    mma_bf16(c[mt][2 * g + 1], ah[mt], rl + 2);
                    mma_bf16(c[mt][2 * g + 1], al[mt], rh + 2);
                }
            }
        }
    }

    __syncthreads();

    #pragma unroll
    for (int mt = 0; mt < 4; mt++) {
        #pragma unroll
        for (int half = 0; half < 2; half++) {
            const int r    = wrow * 64 + mt * 16 + (lid >> 2) + half * 8;
            const int de   = sDe[r];
            const size_t crow = (MODE == 0) ? (size_t)(m0 + r) : (size_t)sPerm[r];
            float* dst = C + crow * (size_t)N;
            #pragma unroll
            for (int nt = 0; nt < 8; nt++) {
                const int n = n0 + wcol * 64 + nt * 8 + (lid & 3) * 2;
                float v0 = c[mt][nt][2 * half + 0];
                float v1 = c[mt][nt][2 * half + 1];
                if (MODE == 1) {
                    v0 += bias[n + 0];
                    v1 += bias[n + 1];
                    if (n + 0 >= de) v0 = 0.f;
                    if (n + 1 >= de) v1 = 0.f;
                }
                *reinterpret_cast<float2*>(dst + n) = make_float2(v0, v1);
            }
        }
    }
}

// ---------------- attention v2: 2 tokens/block ----------------
__global__ void __launch_bounds__(256)
attn_kernel()
{
    __shared__ float s[2][N1];
    __shared__ float s_sc[2][NH * NH];

    const int tid    = threadIdx.x;
    const int sub    = tid >> 7;          // 0..1 token within block
    const int wt     = tid & 127;
    const int tok    = blockIdx.x * 2 + sub;

    // load qkv for this token (128 threads, float4)
    {
        const float4* qkv = reinterpret_cast<const float4*>(&g_qkv[(size_t)tok * N1]);
        float4* ds = reinterpret_cast<float4*>(s[sub]);
        #pragma unroll
        for (int j = 0; j < 5; j++) {               // 576 float4 / 128 = 4.5
            int i = wt + j * 128;
            if (i < N1 / 4) ds[i] = qkv[i];
        }
    }
    __syncthreads();

    // scores: 144 dots
    {
        const float* sq = s[sub];
        #pragma unroll
        for (int rep = 0; rep < 2; rep++) {
            int d = wt + rep * 128;
            if (d < NH * NH) {
                int l = d / NH, sr = d % NH;
                const float4* q = reinterpret_cast<const float4*>(&sq[l * HD]);
                const float4* k = reinterpret_cast<const float4*>(&sq[DIMF + sr * HD]);
                float acc = 0.f;
                #pragma unroll
                for (int j = 0; j < 16; j++) {
                    int jj = (j + sr) & 15;          // rotate start: break stride-64 conflicts
                    float4 qv = q[jj], kv = k[jj];
                    acc += qv.x * kv.x + qv.y * kv.y + qv.z * kv.z + qv.w * kv.w;
                }
                s_sc[sub][d] = acc * ATT_SCALE;
            }
        }
    }
    __syncthreads();

    if (wt < NH) {
        float* sc = &s_sc[sub][wt * NH];
        float mx = -1e30f;
        #pragma unroll
        for (int s2 = 0; s2 < NH; s2++) mx = fmaxf(mx, sc[s2]);
        float ex[NH];
        float sum = 0.f;
        #pragma unroll
        for (int s2 = 0; s2 < NH; s2++) {
            ex[s2] = expf(sc[s2] - mx);
            sum += ex[s2];
        }
        float inv = 1.f / sum;
        #pragma unroll
        for (int s2 = 0; s2 < NH; s2++) sc[s2] = ex[s2] * inv;
    }
    __syncthreads();

    // output: 768 floats / 128 threads = 3 float2 each; emit bf16 hi/lo packed
    {
        const float* sv = &s[sub][2 * DIMF];
        const float* sa = s_sc[sub];
        uint32_t* oh = reinterpret_cast<uint32_t*>(&g_ahi[(size_t)tok * DIMF]);
        uint32_t* ol = reinterpret_cast<uint32_t*>(&g_alo[(size_t)tok * DIMF]);
        #pragma unroll
        for (int j = 0; j < 3; j++) {
            int o2 = wt + j * 128;                 // float2 index 0..383
            int o  = o2 * 2;
            int l  = o >> 6, e = o & 63;
            float a0 = 0.f, a1 = 0.f;
            const float* al = &sa[l * NH];
            #pragma unroll
            for (int sr = 0; sr < NH; sr++) {
                float2 vv = *reinterpret_cast<const float2*>(&sv[sr * HD + e]);
                a0 += al[sr] * vv.x;
                a1 += al[sr] * vv.y;
            }
            float h0 = __bfloat162float(__float2bfloat16_rn(a0));
            float h1 = __bfloat162float(__float2bfloat16_rn(a1));
            oh[o2] = pk2(a0, a1);
            ol[o2] = pk2(a0 - h0, a1 - h1);
        }
    }
}

// ---------------- launch ----------------
extern "C" void kernel_launch(void* const* d_in, const int* in_sizes, int n_in,
                              void* d_out, int out_size)
{
    const float* x      = (const float*)d_in[0];
    const int*   em     = (const int*)  d_in[1];
    const float* qkv_w  = (const float*)d_in[2];
    const float* proj_w = (const float*)d_in[3];
    const float* proj_b = (const float*)d_in[4];
    float*       out    = (float*)d_out;

    static bool init_done = false;
    if (!init_done) {
        cudaFuncSetAttribute(gemm_mma<0>, cudaFuncAttributeMaxDynamicSharedMemorySize, SMEM_DYN);
        cudaFuncSetAttribute(gemm_mma<1>, cudaFuncAttributeMaxDynamicSharedMemorySize, SMEM_DYN);
        init_done = true;
    }

    static float* qkv_ptr = nullptr;
    static __nv_bfloat16 *xhi, *xlo, *ahi, *alo, *wqh, *wql, *wph, *wpl;
    if (!qkv_ptr) {
        cudaGetSymbolAddress((void**)&qkv_ptr, g_qkv);
        cudaGetSymbolAddress((void**)&xhi, g_xhi);
        cudaGetSymbolAddress((void**)&xlo, g_xlo);
        cudaGetSymbolAddress((void**)&ahi, g_ahi);
        cudaGetSymbolAddress((void**)&alo, g_alo);
        cudaGetSymbolAddress((void**)&wqh, g_wqh);
        cudaGetSymbolAddress((void**)&wql, g_wql);
        cudaGetSymbolAddress((void**)&wph, g_wph);
        cudaGetSymbolAddress((void**)&wpl, g_wpl);
    }

    dim3 blk(256);
    dim3 gblk(128);

    sort_hist_kernel<<<64, blk>>>(em);
    sort_scan_kernel<<<1, 32>>>();
    sort_scatter_kernel<<<64, blk>>>(em);
    {
        int tot = (N1 + N2) * (KDIM / 4);
        convert_w_kernel<<<(tot + 255) / 256, blk>>>(qkv_w, proj_w);
    }
    convert_x_kernel<<<(M_TOK * (KDIM / 4) + 255) / 256, blk>>>(x);

    dim3 grid1(N1 / BN, M_TOK / BM);
    gemm_mma<0><<<grid1, gblk, SMEM_DYN>>>(xhi, xlo, wqh, wql, qkv_ptr, N1, nullptr);

    attn_kernel<<<M_TOK / 2, blk>>>();

    int n4 = M_TOK * N2 / 4;
    zero_out_kernel<<<(n4 + 255) / 256, blk>>>((float4*)out, n4);

    dim3 grid2(N2 / BN, M_TOK / BM);
    gemm_mma<1><<<grid2, gblk, SMEM_DYN>>>(ahi, alo, wph, wpl, out, N2, proj_b);
}

// round 9
// speedup vs baseline: 4.2863x; 1.0290x over previous
#include <cuda_runtime.h>
#include <cuda_bf16.h>
#include <math.h>
#include <stdint.h>

// NestedAttention R9: fused one-block sort (warp-aggregated atomics), gemm2
// inlines the zero-fill for masked n-blocks, MMA terms reordered term-major
// to break accumulator RAW chains. Launch order puts gemm1 4th (= the ncu
// capture slot observed in every prior round).

#define DIMF 768
#define NH 12
#define HD 64
#define M_TOK 16384
#define N1 2304
#define N2 768
#define KDIM 768
#define ATT_SCALE 0.125f

#define BM 128
#define BN 128
#define BK 32
#define SKB 80                    // smem row stride bytes (32 bf16 + 16B pad)
#define TILE_B (128 * SKB)        // 10240 B
#define STAGE_B (4 * TILE_B)      // Ah, Al, Bh, Bl
#define SMEM_DYN (2 * STAGE_B)    // 81920 B

// ---------------- scratch ----------------
__device__ float         g_qkv[(size_t)M_TOK * N1];
__device__ __nv_bfloat16 g_xhi[(size_t)M_TOK * KDIM];
__device__ __nv_bfloat16 g_xlo[(size_t)M_TOK * KDIM];
__device__ __nv_bfloat16 g_ahi[(size_t)M_TOK * KDIM];
__device__ __nv_bfloat16 g_alo[(size_t)M_TOK * KDIM];
__device__ __nv_bfloat16 g_wqh[(size_t)N1 * KDIM];
__device__ __nv_bfloat16 g_wql[(size_t)N1 * KDIM];
__device__ __nv_bfloat16 g_wph[(size_t)N2 * KDIM];
__device__ __nv_bfloat16 g_wpl[(size_t)N2 * KDIM];
__device__ int g_perm[M_TOK];
__device__ int g_de[M_TOK];

// ---------------- helpers ----------------
__device__ __forceinline__ uint32_t smem_u32(const void* p) {
    uint32_t a;
    asm("{ .reg .u64 t; cvta.to.shared.u64 t, %1; cvt.u32.u64 %0, t; }" : "=r"(a) : "l"(p));
    return a;
}
__device__ __forceinline__ void cp16(uint32_t dst, const void* src) {
    asm volatile("cp.async.cg.shared.global [%0], [%1], 16;" :: "r"(dst), "l"(src));
}
__device__ __forceinline__ void cp_commit() {
    asm volatile("cp.async.commit_group;");
}
template<int N> __device__ __forceinline__ void cp_wait() {
    asm volatile("cp.async.wait_group %0;" :: "n"(N));
}
__device__ __forceinline__ void ldm_x4(uint32_t* r, uint32_t addr) {
    asm volatile("ldmatrix.sync.aligned.m8n8.x4.shared.b16 {%0,%1,%2,%3}, [%4];"
                 : "=r"(r[0]), "=r"(r[1]), "=r"(r[2]), "=r"(r[3]) : "r"(addr));
}
__device__ __forceinline__ void mma_bf16(float* c, const uint32_t* a, const uint32_t* b) {
    asm volatile(
        "mma.sync.aligned.m16n8k16.row.col.f32.bf16.bf16.f32 "
        "{%0,%1,%2,%3}, {%4,%5,%6,%7}, {%8,%9}, {%0,%1,%2,%3};"
        : "+f"(c[0]), "+f"(c[1]), "+f"(c[2]), "+f"(c[3])
        : "r"(a[0]), "r"(a[1]), "r"(a[2]), "r"(a[3]), "r"(b[0]), "r"(b[1]));
}
__device__ __forceinline__ uint32_t pk2(float a, float b) {
    __nv_bfloat162 t = __floats2bfloat162_rn(a, b);
    return *reinterpret_cast<uint32_t*>(&t);
}

// ---------------- fused sort: one block, warp-aggregated atomics ----------------
__global__ void __launch_bounds__(1024)
sort_fused_kernel(const int* __restrict__ em)
{
    __shared__ int cnt[4];
    __shared__ int base[4];
    const int tid  = threadIdx.x;
    const int lane = tid & 31;

    if (tid < 4) cnt[tid] = 0;
    __syncthreads();

    int ev[16];
    #pragma unroll
    for (int j = 0; j < 16; j++) {
        ev[j] = em[tid + j * 1024];
        unsigned same   = __match_any_sync(0xFFFFFFFFu, ev[j]);
        int      leader = __ffs(same) - 1;
        if (lane == leader) atomicAdd(&cnt[ev[j]], __popc(same));
    }
    __syncthreads();

    if (tid == 0) {
        int acc = 0;
        #pragma unroll
        for (int e = 0; e < 4; e++) { base[e] = acc; acc += cnt[e]; }
        #pragma unroll
        for (int e = 0; e < 4; e++) cnt[e] = base[e];
    }
    __syncthreads();

    #pragma unroll
    for (int j = 0; j < 16; j++) {
        int e = ev[j];
        unsigned same   = __match_any_sync(0xFFFFFFFFu, e);
        int      leader = __ffs(same) - 1;
        int      rank   = __popc(same & ((1u << lane) - 1u));
        int      bp     = 0;
        if (lane == leader) bp = atomicAdd(&cnt[e], __popc(same));
        bp = __shfl_sync(0xFFFFFFFFu, bp, leader);
        int pos = bp + rank;
        int i   = tid + j * 1024;
        g_perm[pos] = i;
        g_de[pos]   = DIMF >> (3 - e);
    }
}

// ---------------- conversions ----------------
__global__ void __launch_bounds__(256)
convert_w_kernel(const float* __restrict__ wq, const float* __restrict__ wp) {
    int i = blockIdx.x * 256 + threadIdx.x;
    const int NQ = N1 * (KDIM / 4);
    if (i >= NQ + N2 * (KDIM / 4)) return;
    const float* src;
    __nv_bfloat16 *hi, *lo;
    int j;
    if (i < NQ) { src = wq; hi = g_wqh; lo = g_wql; j = i; }
    else        { src = wp; hi = g_wph; lo = g_wpl; j = i - NQ; }
    float4 v = reinterpret_cast<const float4*>(src)[j];
    float hx = __bfloat162float(__float2bfloat16_rn(v.x));
    float hy = __bfloat162float(__float2bfloat16_rn(v.y));
    float hz = __bfloat162float(__float2bfloat16_rn(v.z));
    float hw = __bfloat162float(__float2bfloat16_rn(v.w));
    uint2 H = make_uint2(pk2(v.x, v.y), pk2(v.z, v.w));
    uint2 L = make_uint2(pk2(v.x - hx, v.y - hy), pk2(v.z - hz, v.w - hw));
    *reinterpret_cast<uint2*>(&hi[(size_t)j * 4]) = H;
    *reinterpret_cast<uint2*>(&lo[(size_t)j * 4]) = L;
}

__global__ void __launch_bounds__(256)
convert_x_kernel(const float* __restrict__ x) {
    int i = blockIdx.x * 256 + threadIdx.x;
    if (i >= M_TOK * (KDIM / 4)) return;
    int p  = i / (KDIM / 4);
    int c4 = i % (KDIM / 4);
    int t  = g_perm[p];
    int de = g_de[p];
    float4 v = reinterpret_cast<const float4*>(x + (size_t)t * KDIM)[c4];
    int d0 = c4 * 4;
    if (d0 + 0 >= de) v.x = 0.f;
    if (d0 + 1 >= de) v.y = 0.f;
    if (d0 + 2 >= de) v.z = 0.f;
    if (d0 + 3 >= de) v.w = 0.f;
    float hx = __bfloat162float(__float2bfloat16_rn(v.x));
    float hy = __bfloat162float(__float2bfloat16_rn(v.y));
    float hz = __bfloat162float(__float2bfloat16_rn(v.z));
    float hw = __bfloat162float(__float2bfloat16_rn(v.w));
    uint2 H = make_uint2(pk2(v.x, v.y), pk2(v.z, v.w));
    uint2 L = make_uint2(pk2(v.x - hx, v.y - hy), pk2(v.z - hz, v.w - hw));
    size_t o = (size_t)p * KDIM + d0;
    *reinterpret_cast<uint2*>(&g_xhi[o]) = H;
    *reinterpret_cast<uint2*>(&g_xlo[o]) = L;
}

// ---------------- tensor-core GEMM: 4 warps, 64x64 warp tiles ----------------
template<int MODE>
__global__ void __launch_bounds__(128, 2)
gemm_mma(const __nv_bfloat16* __restrict__ Ahi, const __nv_bfloat16* __restrict__ Alo,
         const __nv_bfloat16* __restrict__ Bhi, const __nv_bfloat16* __restrict__ Blo,
         float* __restrict__ C, int N, const float* __restrict__ bias)
{
    __shared__ int sDe[BM];
    __shared__ int sPerm[BM];
    extern __shared__ char dsm[];

    const int tid  = threadIdx.x;
    const int wid  = tid >> 5;
    const int lid  = tid & 31;
    const int wrow = wid >> 1;          // 0..1 -> 64-row slice
    const int wcol = wid & 1;           // 0..1 -> 64-col slice
    const int m0   = blockIdx.y * BM;
    const int n0   = blockIdx.x * BN;

    sDe[tid] = g_de[m0 + tid];
    if (MODE == 1) sPerm[tid] = g_perm[m0 + tid];
    __syncthreads();
    const int kmax = sDe[BM - 1];                 // sorted ascending
    if (MODE == 1 && n0 >= kmax) {
        // fully-masked output block: write zeros directly (row-scattered)
        const size_t crow = (size_t)sPerm[tid];
        float4* dst = reinterpret_cast<float4*>(C + crow * (size_t)N + n0);
        float4 z = make_float4(0.f, 0.f, 0.f, 0.f);
        #pragma unroll
        for (int j = 0; j < BN / 4; j++) dst[j] = z;
        return;
    }
    const int nch = (MODE == 0) ? (kmax / BK) : (KDIM / BK);

    const uint32_t sb = smem_u32(dsm);

    uint32_t aoff[4][2];
    #pragma unroll
    for (int mt = 0; mt < 4; mt++)
        #pragma unroll
        for (int ks = 0; ks < 2; ks++)
            aoff[mt][ks] = (uint32_t)((wrow * 64 + mt * 16 + (lid & 15)) * SKB
                                      + ks * 32 + (lid >> 4) * 16);
    uint32_t boff[4][2];
    {
        int m = lid >> 3;
        #pragma unroll
        for (int g = 0; g < 4; g++)
            #pragma unroll
            for (int ks = 0; ks < 2; ks++)
                boff[g][ks] = (uint32_t)((wcol * 64 + g * 16 + (m >> 1) * 8 + (lid & 7)) * SKB
                                         + ks * 32 + (m & 1) * 16);
    }

    float c[4][8][4];
    #pragma unroll
    for (int mt = 0; mt < 4; mt++)
        #pragma unroll
        for (int nt = 0; nt < 8; nt++)
            #pragma unroll
            for (int q = 0; q < 4; q++) c[mt][nt][q] = 0.f;

    auto fill = [&](int stage, int ic) {
        const int k0 = ic * BK;
        const uint32_t st = sb + stage * STAGE_B;
        #pragma unroll
        for (int t = 0; t < 4; t++) {
            int idx = tid + t * 128;
            int row = idx >> 2;
            int seg = idx & 3;
            uint32_t d = st + row * SKB + seg * 16;
            const __nv_bfloat16* sa = Ahi + (size_t)(m0 + row) * KDIM + k0 + seg * 8;
            const __nv_bfloat16* sl = Alo + (size_t)(m0 + row) * KDIM + k0 + seg * 8;
            const __nv_bfloat16* sh = Bhi + (size_t)(n0 + row) * KDIM + k0 + seg * 8;
            const __nv_bfloat16* sbl= Blo + (size_t)(n0 + row) * KDIM + k0 + seg * 8;
            cp16(d + 0 * TILE_B, sa);
            cp16(d + 1 * TILE_B, sl);
            cp16(d + 2 * TILE_B, sh);
            cp16(d + 3 * TILE_B, sbl);
        }
        cp_commit();
    };

    fill(0, 0);

    for (int ic = 0; ic < nch; ic++) {
        const int b = ic & 1;
        cp_wait<0>();
        __syncthreads();
        if (ic + 1 < nch) fill(b ^ 1, ic + 1);

        const uint32_t st = sb + b * STAGE_B;
        const uint32_t AH = st + 0 * TILE_B, AL = st + 1 * TILE_B;
        const uint32_t BH = st + 2 * TILE_B, BL = st + 3 * TILE_B;

        #pragma unroll
        for (int ks = 0; ks < 2; ks++) {
            uint32_t ah[4][4], al[4][4];
            uint32_t rh[4][4], rl[4][4];
            #pragma unroll
            for (int mt = 0; mt < 4; mt++) {
                ldm_x4(ah[mt], AH + aoff[mt][ks]);
                ldm_x4(al[mt], AL + aoff[mt][ks]);
            }
            #pragma unroll
            for (int g = 0; g < 4; g++) {
                ldm_x4(rh[g], BH + boff[g][ks]);
                ldm_x4(rl[g], BL + boff[g][ks]);
            }
            // term-major ordering: each accumulator's 3 updates are separated
            // by 31 independent HMMAs (no back-to-back RAW on c[][]).
            #pragma unroll
            for (int g = 0; g < 4; g++)
                #pragma unroll
                for (int mt = 0; mt < 4; mt++) {
                    mma_bf16(c[mt][2 * g + 0], ah[mt], rh[g] + 0);
                    mma_bf16(c[mt][2 * g + 1], ah[mt], rh[g] + 2);
                }
            #pragma unroll
            for (int g = 0; g < 4; g++)
                #pragma unroll
                for (int mt = 0; mt < 4; mt++) {
                    mma_bf16(c[mt][2 * g + 0], ah[mt], rl[g] + 0);
                    mma_bf16(c[mt][2 * g + 1], ah[mt], rl[g] + 2);
                }
            #pragma unroll
            for (int g = 0; g < 4; g++)
                #pragma unroll
                for (int mt = 0; mt < 4; mt++) {
                    mma_bf16(c[mt][2 * g + 0], al[mt], rh[g] + 0);
                    mma_bf16(c[mt][2 * g + 1], al[mt], rh[g] + 2);
                }
        }
    }

    __syncthreads();

    #pragma unroll
    for (int mt = 0; mt < 4; mt++) {
        #pragma unroll
        for (int half = 0; half < 2; half++) {
            const int r    = wrow * 64 + mt * 16 + (lid >> 2) + half * 8;
            const int de   = sDe[r];
            const size_t crow = (MODE == 0) ? (size_t)(m0 + r) : (size_t)sPerm[r];
            float* dst = C + crow * (size_t)N;
            #pragma unroll
            for (int nt = 0; nt < 8; nt++) {
                const int n = n0 + wcol * 64 + nt * 8 + (lid & 3) * 2;
                float v0 = c[mt][nt][2 * half + 0];
                float v1 = c[mt][nt][2 * half + 1];
                if (MODE == 1) {
                    v0 += bias[n + 0];
                    v1 += bias[n + 1];
                    if (n + 0 >= de) v0 = 0.f;
                    if (n + 1 >= de) v1 = 0.f;
                }
                *reinterpret_cast<float2*>(dst + n) = make_float2(v0, v1);
            }
        }
    }
}

// ---------------- attention: 2 tokens/block ----------------
__global__ void __launch_bounds__(256)
attn_kernel()
{
    __shared__ float s[2][N1];
    __shared__ float s_sc[2][NH * NH];

    const int tid = threadIdx.x;
    const int sub = tid >> 7;
    const int wt  = tid & 127;
    const int tok = blockIdx.x * 2 + sub;

    {
        const float4* qkv = reinterpret_cast<const float4*>(&g_qkv[(size_t)tok * N1]);
        float4* ds = reinterpret_cast<float4*>(s[sub]);
        #pragma unroll
        for (int j = 0; j < 5; j++) {
            int i = wt + j * 128;
            if (i < N1 / 4) ds[i] = qkv[i];
        }
    }
    __syncthreads();

    {
        const float* sq = s[sub];
        #pragma unroll
        for (int rep = 0; rep < 2; rep++) {
            int d = wt + rep * 128;
            if (d < NH * NH) {
                int l = d / NH, sr = d % NH;
                const float4* q = reinterpret_cast<const float4*>(&sq[l * HD]);
                const float4* k = reinterpret_cast<const float4*>(&sq[DIMF + sr * HD]);
                float acc = 0.f;
                #pragma unroll
                for (int j = 0; j < 16; j++) {
                    int jj = (j + sr) & 15;
                    float4 qv = q[jj], kv = k[jj];
                    acc += qv.x * kv.x + qv.y * kv.y + qv.z * kv.z + qv.w * kv.w;
                }
                s_sc[sub][d] = acc * ATT_SCALE;
            }
        }
    }
    __syncthreads();

    if (wt < NH) {
        float* sc = &s_sc[sub][wt * NH];
        float mx = -1e30f;
        #pragma unroll
        for (int s2 = 0; s2 < NH; s2++) mx = fmaxf(mx, sc[s2]);
        float ex[NH];
        float sum = 0.f;
        #pragma unroll
        for (int s2 = 0; s2 < NH; s2++) {
            ex[s2] = expf(sc[s2] - mx);
            sum += ex[s2];
        }
        float inv = 1.f / sum;
        #pragma unroll
        for (int s2 = 0; s2 < NH; s2++) sc[s2] = ex[s2] * inv;
    }
    __syncthreads();

    {
        const float* sv = &s[sub][2 * DIMF];
        const float* sa = s_sc[sub];
        uint32_t* oh = reinterpret_cast<uint32_t*>(&g_ahi[(size_t)tok * DIMF]);
        uint32_t* ol = reinterpret_cast<uint32_t*>(&g_alo[(size_t)tok * DIMF]);
        #pragma unroll
        for (int j = 0; j < 3; j++) {
            int o2 = wt + j * 128;
            int o  = o2 * 2;
            int l  = o >> 6, e = o & 63;
            float a0 = 0.f, a1 = 0.f;
            const float* al = &sa[l * NH];
            #pragma unroll
            for (int sr = 0; sr < NH; sr++) {
                float2 vv = *reinterpret_cast<const float2*>(&sv[sr * HD + e]);
                a0 += al[sr] * vv.x;
                a1 += al[sr] * vv.y;
            }
            float h0 = __bfloat162float(__float2bfloat16_rn(a0));
            float h1 = __bfloat162float(__float2bfloat16_rn(a1));
            oh[o2] = pk2(a0, a1);
            ol[o2] = pk2(a0 - h0, a1 - h1);
        }
    }
}

// ---------------- launch ----------------
extern "C" void kernel_launch(void* const* d_in, const int* in_sizes, int n_in,
                              void* d_out, int out_size)
{
    const float* x      = (const float*)d_in[0];
    const int*   em     = (const int*)  d_in[1];
    const float* qkv_w  = (const float*)d_in[2];
    const float* proj_w = (const float*)d_in[3];
    const float* proj_b = (const float*)d_in[4];
    float*       out    = (float*)d_out;

    static bool init_done = false;
    if (!init_done) {
        cudaFuncSetAttribute(gemm_mma<0>, cudaFuncAttributeMaxDynamicSharedMemorySize, SMEM_DYN);
        cudaFuncSetAttribute(gemm_mma<1>, cudaFuncAttributeMaxDynamicSharedMemorySize, SMEM_DYN);
        init_done = true;
    }

    static float* qkv_ptr = nullptr;
    static __nv_bfloat16 *xhi, *xlo, *ahi, *alo, *wqh, *wql, *wph, *wpl;
    if (!qkv_ptr) {
        cudaGetSymbolAddress((void**)&qkv_ptr, g_qkv);
        cudaGetSymbolAddress((void**)&xhi, g_xhi);
        cudaGetSymbolAddress((void**)&xlo, g_xlo);
        cudaGetSymbolAddress((void**)&ahi, g_ahi);
        cudaGetSymbolAddress((void**)&alo, g_alo);
        cudaGetSymbolAddress((void**)&wqh, g_wqh);
        cudaGetSymbolAddress((void**)&wql, g_wql);
        cudaGetSymbolAddress((void**)&wph, g_wph);
        cudaGetSymbolAddress((void**)&wpl, g_wpl);
    }

    dim3 blk(256);
    dim3 gblk(128);

    sort_fused_kernel<<<1, 1024>>>(em);                                      // 1
    {
        int tot = (N1 + N2) * (KDIM / 4);
        convert_w_kernel<<<(tot + 255) / 256, blk>>>(qkv_w, proj_w);         // 2
    }
    convert_x_kernel<<<(M_TOK * (KDIM / 4) + 255) / 256, blk>>>(x);          // 3

    dim3 grid1(N1 / BN, M_TOK / BM);
    gemm_mma<0><<<grid1, gblk, SMEM_DYN>>>(xhi, xlo, wqh, wql, qkv_ptr, N1, nullptr); // 4

    attn_kernel<<<M_TOK / 2, blk>>>();                                       // 5

    dim3 grid2(N2 / BN, M_TOK / BM);
    gemm_mma<1><<<grid2, gblk, SMEM_DYN>>>(ahi, alo, wph, wpl, out, N2, proj_b); // 6
}

// round 11
// speedup vs baseline: 4.4364x; 1.0350x over previous
#include <cuda_runtime.h>
#include <cuda_bf16.h>
#include <math.h>
#include <stdint.h>

// NestedAttention R10 (resubmit — infra container failure, kernel never ran):
// attention de-chained (4-way score accumulators, 2x2 AV partials, __expf);
// GEMM mainloop reordered LDSM-first -> fill -> MMA to shrink the joint stall
// window at each chunk boundary.

#define DIMF 768
#define NH 12
#define HD 64
#define M_TOK 16384
#define N1 2304
#define N2 768
#define KDIM 768
#define ATT_SCALE 0.125f

#define BM 128
#define BN 128
#define BK 32
#define SKB 80                    // smem row stride bytes (32 bf16 + 16B pad)
#define TILE_B (128 * SKB)        // 10240 B
#define STAGE_B (4 * TILE_B)      // Ah, Al, Bh, Bl
#define SMEM_DYN (2 * STAGE_B)    // 81920 B

// ---------------- scratch ----------------
__device__ float         g_qkv[(size_t)M_TOK * N1];
__device__ __nv_bfloat16 g_xhi[(size_t)M_TOK * KDIM];
__device__ __nv_bfloat16 g_xlo[(size_t)M_TOK * KDIM];
__device__ __nv_bfloat16 g_ahi[(size_t)M_TOK * KDIM];
__device__ __nv_bfloat16 g_alo[(size_t)M_TOK * KDIM];
__device__ __nv_bfloat16 g_wqh[(size_t)N1 * KDIM];
__device__ __nv_bfloat16 g_wql[(size_t)N1 * KDIM];
__device__ __nv_bfloat16 g_wph[(size_t)N2 * KDIM];
__device__ __nv_bfloat16 g_wpl[(size_t)N2 * KDIM];
__device__ int g_perm[M_TOK];
__device__ int g_de[M_TOK];

// ---------------- helpers ----------------
__device__ __forceinline__ uint32_t smem_u32(const void* p) {
    uint32_t a;
    asm("{ .reg .u64 t; cvta.to.shared.u64 t, %1; cvt.u32.u64 %0, t; }" : "=r"(a) : "l"(p));
    return a;
}
__device__ __forceinline__ void cp16(uint32_t dst, const void* src) {
    asm volatile("cp.async.cg.shared.global [%0], [%1], 16;" :: "r"(dst), "l"(src));
}
__device__ __forceinline__ void cp_commit() {
    asm volatile("cp.async.commit_group;");
}
template<int N> __device__ __forceinline__ void cp_wait() {
    asm volatile("cp.async.wait_group %0;" :: "n"(N));
}
__device__ __forceinline__ void ldm_x4(uint32_t* r, uint32_t addr) {
    asm volatile("ldmatrix.sync.aligned.m8n8.x4.shared.b16 {%0,%1,%2,%3}, [%4];"
                 : "=r"(r[0]), "=r"(r[1]), "=r"(r[2]), "=r"(r[3]) : "r"(addr));
}
__device__ __forceinline__ void mma_bf16(float* c, const uint32_t* a, const uint32_t* b) {
    asm volatile(
        "mma.sync.aligned.m16n8k16.row.col.f32.bf16.bf16.f32 "
        "{%0,%1,%2,%3}, {%4,%5,%6,%7}, {%8,%9}, {%0,%1,%2,%3};"
        : "+f"(c[0]), "+f"(c[1]), "+f"(c[2]), "+f"(c[3])
        : "r"(a[0]), "r"(a[1]), "r"(a[2]), "r"(a[3]), "r"(b[0]), "r"(b[1]));
}
__device__ __forceinline__ uint32_t pk2(float a, float b) {
    __nv_bfloat162 t = __floats2bfloat162_rn(a, b);
    return *reinterpret_cast<uint32_t*>(&t);
}

// ---------------- fused sort: one block, warp-aggregated atomics ----------------
__global__ void __launch_bounds__(1024)
sort_fused_kernel(const int* __restrict__ em)
{
    __shared__ int cnt[4];
    __shared__ int base[4];
    const int tid  = threadIdx.x;
    const int lane = tid & 31;

    if (tid < 4) cnt[tid] = 0;
    __syncthreads();

    int ev[16];
    #pragma unroll
    for (int j = 0; j < 16; j++) {
        ev[j] = em[tid + j * 1024];
        unsigned same   = __match_any_sync(0xFFFFFFFFu, ev[j]);
        int      leader = __ffs(same) - 1;
        if (lane == leader) atomicAdd(&cnt[ev[j]], __popc(same));
    }
    __syncthreads();

    if (tid == 0) {
        int acc = 0;
        #pragma unroll
        for (int e = 0; e < 4; e++) { base[e] = acc; acc += cnt[e]; }
        #pragma unroll
        for (int e = 0; e < 4; e++) cnt[e] = base[e];
    }
    __syncthreads();

    #pragma unroll
    for (int j = 0; j < 16; j++) {
        int e = ev[j];
        unsigned same   = __match_any_sync(0xFFFFFFFFu, e);
        int      leader = __ffs(same) - 1;
        int      rank   = __popc(same & ((1u << lane) - 1u));
        int      bp     = 0;
        if (lane == leader) bp = atomicAdd(&cnt[e], __popc(same));
        bp = __shfl_sync(0xFFFFFFFFu, bp, leader);
        int pos = bp + rank;
        int i   = tid + j * 1024;
        g_perm[pos] = i;
        g_de[pos]   = DIMF >> (3 - e);
    }
}

// ---------------- conversions ----------------
__global__ void __launch_bounds__(256)
convert_w_kernel(const float* __restrict__ wq, const float* __restrict__ wp) {
    int i = blockIdx.x * 256 + threadIdx.x;
    const int NQ = N1 * (KDIM / 4);
    if (i >= NQ + N2 * (KDIM / 4)) return;
    const float* src;
    __nv_bfloat16 *hi, *lo;
    int j;
    if (i < NQ) { src = wq; hi = g_wqh; lo = g_wql; j = i; }
    else        { src = wp; hi = g_wph; lo = g_wpl; j = i - NQ; }
    float4 v = reinterpret_cast<const float4*>(src)[j];
    float hx = __bfloat162float(__float2bfloat16_rn(v.x));
    float hy = __bfloat162float(__float2bfloat16_rn(v.y));
    float hz = __bfloat162float(__float2bfloat16_rn(v.z));
    float hw = __bfloat162float(__float2bfloat16_rn(v.w));
    uint2 H = make_uint2(pk2(v.x, v.y), pk2(v.z, v.w));
    uint2 L = make_uint2(pk2(v.x - hx, v.y - hy), pk2(v.z - hz, v.w - hw));
    *reinterpret_cast<uint2*>(&hi[(size_t)j * 4]) = H;
    *reinterpret_cast<uint2*>(&lo[(size_t)j * 4]) = L;
}

__global__ void __launch_bounds__(256)
convert_x_kernel(const float* __restrict__ x) {
    int i = blockIdx.x * 256 + threadIdx.x;
    if (i >= M_TOK * (KDIM / 4)) return;
    int p  = i / (KDIM / 4);
    int c4 = i % (KDIM / 4);
    int t  = g_perm[p];
    int de = g_de[p];
    float4 v = reinterpret_cast<const float4*>(x + (size_t)t * KDIM)[c4];
    int d0 = c4 * 4;
    if (d0 + 0 >= de) v.x = 0.f;
    if (d0 + 1 >= de) v.y = 0.f;
    if (d0 + 2 >= de) v.z = 0.f;
    if (d0 + 3 >= de) v.w = 0.f;
    float hx = __bfloat162float(__float2bfloat16_rn(v.x));
    float hy = __bfloat162float(__float2bfloat16_rn(v.y));
    float hz = __bfloat162float(__float2bfloat16_rn(v.z));
    float hw = __bfloat162float(__float2bfloat16_rn(v.w));
    uint2 H = make_uint2(pk2(v.x, v.y), pk2(v.z, v.w));
    uint2 L = make_uint2(pk2(v.x - hx, v.y - hy), pk2(v.z - hz, v.w - hw));
    size_t o = (size_t)p * KDIM + d0;
    *reinterpret_cast<uint2*>(&g_xhi[o]) = H;
    *reinterpret_cast<uint2*>(&g_xlo[o]) = L;
}

// ---------------- tensor-core GEMM: 4 warps, 64x64 warp tiles ----------------
template<int MODE>
__global__ void __launch_bounds__(128, 2)
gemm_mma(const __nv_bfloat16* __restrict__ Ahi, const __nv_bfloat16* __restrict__ Alo,
         const __nv_bfloat16* __restrict__ Bhi, const __nv_bfloat16* __restrict__ Blo,
         float* __restrict__ C, int N, const float* __restrict__ bias)
{
    __shared__ int sDe[BM];
    __shared__ int sPerm[BM];
    extern __shared__ char dsm[];

    const int tid  = threadIdx.x;
    const int wid  = tid >> 5;
    const int lid  = tid & 31;
    const int wrow = wid >> 1;
    const int wcol = wid & 1;
    const int m0   = blockIdx.y * BM;
    const int n0   = blockIdx.x * BN;

    sDe[tid] = g_de[m0 + tid];
    if (MODE == 1) sPerm[tid] = g_perm[m0 + tid];
    __syncthreads();
    const int kmax = sDe[BM - 1];                 // sorted ascending
    if (MODE == 1 && n0 >= kmax) {
        const size_t crow = (size_t)sPerm[tid];
        float4* dst = reinterpret_cast<float4*>(C + crow * (size_t)N + n0);
        float4 z = make_float4(0.f, 0.f, 0.f, 0.f);
        #pragma unroll
        for (int j = 0; j < BN / 4; j++) dst[j] = z;
        return;
    }
    const int nch = (MODE == 0) ? (kmax / BK) : (KDIM / BK);

    const uint32_t sb = smem_u32(dsm);

    uint32_t aoff[4][2];
    #pragma unroll
    for (int mt = 0; mt < 4; mt++)
        #pragma unroll
        for (int ks = 0; ks < 2; ks++)
            aoff[mt][ks] = (uint32_t)((wrow * 64 + mt * 16 + (lid & 15)) * SKB
                                      + ks * 32 + (lid >> 4) * 16);
    uint32_t boff[4][2];
    {
        int m = lid >> 3;
        #pragma unroll
        for (int g = 0; g < 4; g++)
            #pragma unroll
            for (int ks = 0; ks < 2; ks++)
                boff[g][ks] = (uint32_t)((wcol * 64 + g * 16 + (m >> 1) * 8 + (lid & 7)) * SKB
                                         + ks * 32 + (m & 1) * 16);
    }

    float c[4][8][4];
    #pragma unroll
    for (int mt = 0; mt < 4; mt++)
        #pragma unroll
        for (int nt = 0; nt < 8; nt++)
            #pragma unroll
            for (int q = 0; q < 4; q++) c[mt][nt][q] = 0.f;

    auto fill = [&](int stage, int ic) {
        const int k0 = ic * BK;
        const uint32_t st = sb + stage * STAGE_B;
        #pragma unroll
        for (int t = 0; t < 4; t++) {
            int idx = tid + t * 128;
            int row = idx >> 2;
            int seg = idx & 3;
            uint32_t d = st + row * SKB + seg * 16;
            const __nv_bfloat16* sa = Ahi + (size_t)(m0 + row) * KDIM + k0 + seg * 8;
            const __nv_bfloat16* sl = Alo + (size_t)(m0 + row) * KDIM + k0 + seg * 8;
            const __nv_bfloat16* sh = Bhi + (size_t)(n0 + row) * KDIM + k0 + seg * 8;
            const __nv_bfloat16* sbl= Blo + (size_t)(n0 + row) * KDIM + k0 + seg * 8;
            cp16(d + 0 * TILE_B, sa);
            cp16(d + 1 * TILE_B, sl);
            cp16(d + 2 * TILE_B, sh);
            cp16(d + 3 * TILE_B, sbl);
        }
        cp_commit();
    };

    fill(0, 0);

    for (int ic = 0; ic < nch; ic++) {
        const int b = ic & 1;
        cp_wait<0>();
        __syncthreads();

        const uint32_t st = sb + b * STAGE_B;
        const uint32_t AH = st + 0 * TILE_B, AL = st + 1 * TILE_B;
        const uint32_t BH = st + 2 * TILE_B, BL = st + 3 * TILE_B;

        #pragma unroll
        for (int ks = 0; ks < 2; ks++) {
            // fragment loads FIRST (LDSM issues before prefetch LDGSTS)
            uint32_t ah[4][4], al[4][4];
            uint32_t rh[4][4], rl[4][4];
            #pragma unroll
            for (int mt = 0; mt < 4; mt++) {
                ldm_x4(ah[mt], AH + aoff[mt][ks]);
                ldm_x4(al[mt], AL + aoff[mt][ks]);
            }
            #pragma unroll
            for (int g = 0; g < 4; g++) {
                ldm_x4(rh[g], BH + boff[g][ks]);
                ldm_x4(rl[g], BL + boff[g][ks]);
            }
            // prefetch next stage while the LDSM latency drains
            if (ks == 0 && ic + 1 < nch) fill(b ^ 1, ic + 1);

            // term-major: each accumulator's updates 32 HMMAs apart
            #pragma unroll
            for (int g = 0; g < 4; g++)
                #pragma unroll
                for (int mt = 0; mt < 4; mt++) {
                    mma_bf16(c[mt][2 * g + 0], ah[mt], rh[g] + 0);
                    mma_bf16(c[mt][2 * g + 1], ah[mt], rh[g] + 2);
                }
            #pragma unroll
            for (int g = 0; g < 4; g++)
                #pragma unroll
                for (int mt = 0; mt < 4; mt++) {
                    mma_bf16(c[mt][2 * g + 0], ah[mt], rl[g] + 0);
                    mma_bf16(c[mt][2 * g + 1], ah[mt], rl[g] + 2);
                }
            #pragma unroll
            for (int g = 0; g < 4; g++)
                #pragma unroll
                for (int mt = 0; mt < 4; mt++) {
                    mma_bf16(c[mt][2 * g + 0], al[mt], rh[g] + 0);
                    mma_bf16(c[mt][2 * g + 1], al[mt], rh[g] + 2);
                }
        }
    }

    __syncthreads();

    #pragma unroll
    for (int mt = 0; mt < 4; mt++) {
        #pragma unroll
        for (int half = 0; half < 2; half++) {
            const int r    = wrow * 64 + mt * 16 + (lid >> 2) + half * 8;
            const int de   = sDe[r];
            const size_t crow = (MODE == 0) ? (size_t)(m0 + r) : (size_t)sPerm[r];
            float* dst = C + crow * (size_t)N;
            #pragma unroll
            for (int nt = 0; nt < 8; nt++) {
                const int n = n0 + wcol * 64 + nt * 8 + (lid & 3) * 2;
                float v0 = c[mt][nt][2 * half + 0];
                float v1 = c[mt][nt][2 * half + 1];
                if (MODE == 1) {
                    v0 += bias[n + 0];
                    v1 += bias[n + 1];
                    if (n + 0 >= de) v0 = 0.f;
                    if (n + 1 >= de) v1 = 0.f;
                }
                *reinterpret_cast<float2*>(dst + n) = make_float2(v0, v1);
            }
        }
    }
}

// ---------------- attention v3: 2 tokens/block, de-chained ----------------
__global__ void __launch_bounds__(256)
attn_kernel()
{
    __shared__ float s[2][N1];
    __shared__ float s_sc[2][NH * NH];

    const int tid = threadIdx.x;
    const int sub = tid >> 7;
    const int wt  = tid & 127;
    const int tok = blockIdx.x * 2 + sub;

    {
        const float4* qkv = reinterpret_cast<const float4*>(&g_qkv[(size_t)tok * N1]);
        float4* ds = reinterpret_cast<float4*>(s[sub]);
        #pragma unroll
        for (int j = 0; j < 5; j++) {
            int i = wt + j * 128;
            if (i < N1 / 4) ds[i] = qkv[i];
        }
    }
    __syncthreads();

    // scores: 4 independent component accumulators per dot
    {
        const float* sq = s[sub];
        #pragma unroll
        for (int rep = 0; rep < 2; rep++) {
            int d = wt + rep * 128;
            if (d < NH * NH) {
                int l = d / NH, sr = d % NH;
                const float4* q = reinterpret_cast<const float4*>(&sq[l * HD]);
                const float4* k = reinterpret_cast<const float4*>(&sq[DIMF + sr * HD]);
                float a0 = 0.f, a1 = 0.f, a2 = 0.f, a3 = 0.f;
                #pragma unroll
                for (int j = 0; j < 16; j++) {
                    int jj = (j + sr) & 15;          // rotate: break stride-64 conflicts
                    float4 qv = q[jj], kv = k[jj];
                    a0 += qv.x * kv.x;
                    a1 += qv.y * kv.y;
                    a2 += qv.z * kv.z;
                    a3 += qv.w * kv.w;
                }
                s_sc[sub][d] = ((a0 + a1) + (a2 + a3)) * ATT_SCALE;
            }
        }
    }
    __syncthreads();

    if (wt < NH) {
        float* sc = &s_sc[sub][wt * NH];
        float mx = -1e30f;
        #pragma unroll
        for (int s2 = 0; s2 < NH; s2++) mx = fmaxf(mx, sc[s2]);
        float ex[NH];
        float sum = 0.f;
        #pragma unroll
        for (int s2 = 0; s2 < NH; s2++) {
            ex[s2] = __expf(sc[s2] - mx);
            sum += ex[s2];
        }
        float inv = 1.f / sum;
        #pragma unroll
        for (int s2 = 0; s2 < NH; s2++) sc[s2] = ex[s2] * inv;
    }
    __syncthreads();

    // AV: 2x2 partial accumulators (sr split even/odd)
    {
        const float* sv = &s[sub][2 * DIMF];
        const float* sa = s_sc[sub];
        uint32_t* oh = reinterpret_cast<uint32_t*>(&g_ahi[(size_t)tok * DIMF]);
        uint32_t* ol = reinterpret_cast<uint32_t*>(&g_alo[(size_t)tok * DIMF]);
        #pragma unroll
        for (int j = 0; j < 3; j++) {
            int o2 = wt + j * 128;
            int o  = o2 * 2;
            int l  = o >> 6, e = o & 63;
            float p00 = 0.f, p01 = 0.f, p10 = 0.f, p11 = 0.f;
            const float* al = &sa[l * NH];
            #pragma unroll
            for (int sr = 0; sr < NH; sr += 2) {
                float w0 = al[sr], w1 = al[sr + 1];
                float2 v0 = *reinterpret_cast<const float2*>(&sv[sr * HD + e]);
                float2 v1 = *reinterpret_cast<const float2*>(&sv[(sr + 1) * HD + e]);
                p00 += w0 * v0.x;
                p01 += w0 * v0.y;
                p10 += w1 * v1.x;
                p11 += w1 * v1.y;
            }
            float a0 = p00 + p10;
            float a1 = p01 + p11;
            float h0 = __bfloat162float(__float2bfloat16_rn(a0));
            float h1 = __bfloat162float(__float2bfloat16_rn(a1));
            oh[o2] = pk2(a0, a1);
            ol[o2] = pk2(a0 - h0, a1 - h1);
        }
    }
}

// ---------------- launch ----------------
extern "C" void kernel_launch(void* const* d_in, const int* in_sizes, int n_in,
                              void* d_out, int out_size)
{
    const float* x      = (const float*)d_in[0];
    const int*   em     = (const int*)  d_in[1];
    const float* qkv_w  = (const float*)d_in[2];
    const float* proj_w = (const float*)d_in[3];
    const float* proj_b = (const float*)d_in[4];
    float*       out    = (float*)d_out;

    static bool init_done = false;
    if (!init_done) {
        cudaFuncSetAttribute(gemm_mma<0>, cudaFuncAttributeMaxDynamicSharedMemorySize, SMEM_DYN);
        cudaFuncSetAttribute(gemm_mma<1>, cudaFuncAttributeMaxDynamicSharedMemorySize, SMEM_DYN);
        init_done = true;
    }

    static float* qkv_ptr = nullptr;
    static __nv_bfloat16 *xhi, *xlo, *ahi, *alo, *wqh, *wql, *wph, *wpl;
    if (!qkv_ptr) {
        cudaGetSymbolAddress((void**)&qkv_ptr, g_qkv);
        cudaGetSymbolAddress((void**)&xhi, g_xhi);
        cudaGetSymbolAddress((void**)&xlo, g_xlo);
        cudaGetSymbolAddress((void**)&ahi, g_ahi);
        cudaGetSymbolAddress((void**)&alo, g_alo);
        cudaGetSymbolAddress((void**)&wqh, g_wqh);
        cudaGetSymbolAddress((void**)&wql, g_wql);
        cudaGetSymbolAddress((void**)&wph, g_wph);
        cudaGetSymbolAddress((void**)&wpl, g_wpl);
    }

    dim3 blk(256);
    dim3 gblk(128);

    sort_fused_kernel<<<1, 1024>>>(em);                                      // 1
    {
        int tot = (N1 + N2) * (KDIM / 4);
        convert_w_kernel<<<(tot + 255) / 256, blk>>>(qkv_w, proj_w);         // 2
    }
    convert_x_kernel<<<(M_TOK * (KDIM / 4) + 255) / 256, blk>>>(x);          // 3

    dim3 grid1(N1 / BN, M_TOK / BM);
    gemm_mma<0><<<grid1, gblk, SMEM_DYN>>>(xhi, xlo, wqh, wql, qkv_ptr, N1, nullptr); // 4

    attn_kernel<<<M_TOK / 2, blk>>>();                                       // 5

    dim3 grid2(N2 / BN, M_TOK / BM);
    gemm_mma<1><<<grid2, gblk, SMEM_DYN>>>(ahi, alo, wph, wpl, out, N2, proj_b); // 6
}